// round 8
// baseline (speedup 1.0000x reference)
#include <cuda_runtime.h>
#include <cuda_bf16.h>
#include <math.h>
#include <stdint.h>

// Problem constants
#define SEQ    2048
#define DIN    4096
#define DOUT   4096
#define NH     32
#define NKV    8
#define HD     128
#define GROUP  4

// Scratch buffers
__device__ float g_Q[SEQ * DOUT];
__device__ float g_K[SEQ * (NKV * HD)];
__device__ float g_V[SEQ * (NKV * HD)];
__device__ float g_ctx[SEQ * DOUT];

__device__ __forceinline__ float f2tf32(float x) {
    float r;
    asm("cvt.rna.tf32.f32 %0, %1;" : "=f"(r) : "f"(x));
    return r;
}

__device__ __forceinline__ uint32_t cvt_u(uint32_t u) {
    float f = __uint_as_float(u);
    asm("cvt.rna.tf32.f32 %0, %1;" : "=f"(f) : "f"(f));
    return __float_as_uint(f);
}

__device__ __forceinline__ void mma_tf32(float* c, const uint32_t* a, const uint32_t* b) {
    asm volatile(
        "mma.sync.aligned.m16n8k8.row.col.f32.tf32.tf32.f32 "
        "{%0,%1,%2,%3}, {%4,%5,%6,%7}, {%8,%9}, {%0,%1,%2,%3};"
        : "+f"(c[0]), "+f"(c[1]), "+f"(c[2]), "+f"(c[3])
        : "r"(a[0]), "r"(a[1]), "r"(a[2]), "r"(a[3]), "r"(b[0]), "r"(b[1]));
}

__device__ __forceinline__ uint32_t smem_u32(const void* p) {
    uint32_t a;
    asm("{ .reg .u64 t; cvta.to.shared.u64 t, %1; cvt.u32.u64 %0, t; }"
        : "=r"(a) : "l"(p));
    return a;
}

__device__ __forceinline__ void cp16(uint32_t dst, const float* src) {
    asm volatile("cp.async.cg.shared.global [%0], [%1], 16;"
                 :: "r"(dst), "l"(src) : "memory");
}
#define CP_COMMIT() asm volatile("cp.async.commit_group;" ::: "memory")
#define CP_WAIT(n)  asm volatile("cp.async.wait_group %0;" :: "n"(n) : "memory")

// ===========================================================================
// cp.async tf32 GEMM core (unchanged from Round 5 — validated)
// ===========================================================================
#define GS 3
#define STAGE_BYTES 32768
#define GEMM_SMEM (GS * STAGE_BYTES)

__device__ __forceinline__ void gemm_core(
    const float* __restrict__ A, const float* __restrict__ B,
    float* __restrict__ C, int K, int ldc, int bm)
{
    extern __shared__ char sbuf[];
    const uint32_t sbase = smem_u32(sbuf);
    const int tid  = threadIdx.x;
    const int lane = tid & 31;
    const int warp = tid >> 5;
    const int gID  = lane >> 2;
    const int tig  = lane & 3;
    const int wm   = (warp & 1) * 64;
    const int wn   = (warp >> 1) * 64;

    const int fr = tid >> 3;
    const int fc = tid & 7;

    float acc[4][8][4];
#pragma unroll
    for (int mi = 0; mi < 4; mi++)
#pragma unroll
        for (int ni = 0; ni < 8; ni++)
#pragma unroll
            for (int j = 0; j < 4; j++) acc[mi][ni][j] = 0.f;

    const int nK = K >> 5;

    auto fill = [&](int st, int kt) {
        const uint32_t dA = sbase + st * STAGE_BYTES;
        const uint32_t dB = dA + 16384;
        const float* gA = A + (size_t)bm * K + kt * 32;
        const float* gB = B + (size_t)kt * 32;
#pragma unroll
        for (int i = 0; i < 8; i++) {
            const int r = fr + i * 16;
            const uint32_t sw = (uint32_t)(r * 128 + ((fc ^ (r & 7)) * 16));
            cp16(dA + sw, gA + (size_t)r * K + fc * 4);
            cp16(dB + sw, gB + (size_t)r * K + fc * 4);
        }
    };

#pragma unroll
    for (int s = 0; s < GS - 1; s++) {
        if (s < nK) fill(s, s);
        CP_COMMIT();
    }

    for (int kt = 0; kt < nK; kt++) {
        const int nxt = kt + GS - 1;
        if (nxt < nK) fill(nxt % GS, nxt);
        CP_COMMIT();
        CP_WAIT(2);
        __syncthreads();

        const uint32_t* Sa = (const uint32_t*)(sbuf + (kt % GS) * STAGE_BYTES);
        const uint32_t* Sb = Sa + 4096;

#pragma unroll
        for (int kk = 0; kk < 4; kk++) {
            const int K4 = kk * 2;
            const int x0 = ((K4 ^ gID) * 4 + tig);
            const int x1 = (((K4 + 1) ^ gID) * 4 + tig);

            uint32_t af[4][4], bf[8][2];
#pragma unroll
            for (int mi = 0; mi < 4; mi++) {
                const int r = wm + mi * 16 + gID;
                af[mi][0] = cvt_u(Sa[r * 32 + x0]);
                af[mi][1] = cvt_u(Sa[(r + 8) * 32 + x0]);
                af[mi][2] = cvt_u(Sa[r * 32 + x1]);
                af[mi][3] = cvt_u(Sa[(r + 8) * 32 + x1]);
            }
#pragma unroll
            for (int ni = 0; ni < 8; ni++) {
                const int n = wn + ni * 8 + gID;
                bf[ni][0] = cvt_u(Sb[n * 32 + x0]);
                bf[ni][1] = cvt_u(Sb[n * 32 + x1]);
            }
#pragma unroll
            for (int mi = 0; mi < 4; mi++)
#pragma unroll
                for (int ni = 0; ni < 8; ni++)
                    mma_tf32(acc[mi][ni], af[mi], bf[ni]);
        }
        __syncthreads();
    }

#pragma unroll
    for (int mi = 0; mi < 4; mi++) {
        const int r0 = bm + wm + mi * 16 + gID;
#pragma unroll
        for (int ni = 0; ni < 8; ni++) {
            const int c0 = wn + ni * 8 + tig * 2;
            const float* c = acc[mi][ni];
            *(float2*)(C + (size_t)r0 * ldc + c0)       = make_float2(c[0], c[1]);
            *(float2*)(C + (size_t)(r0 + 8) * ldc + c0) = make_float2(c[2], c[3]);
        }
    }
}

__global__ __launch_bounds__(128, 2) void gemm_qkv(
    const float* __restrict__ x,
    const float* __restrict__ Wq, const float* __restrict__ Wk,
    const float* __restrict__ Wv,
    float* __restrict__ Q, float* __restrict__ Ko, float* __restrict__ Vo)
{
    const int bn = blockIdx.x;
    const int bm = blockIdx.y * 128;
    const float* B;
    float* C;
    int ldc, coff;
    if (bn < 32)      { B = Wq; C = Q;  ldc = DOUT; coff = bn * 128; }
    else if (bn < 40) { B = Wk; C = Ko; ldc = NKV * HD; coff = (bn - 32) * 128; }
    else              { B = Wv; C = Vo; ldc = NKV * HD; coff = (bn - 40) * 128; }
    gemm_core(x, B + (size_t)coff * DIN, C + coff, DIN, ldc, bm);
}

__global__ __launch_bounds__(128, 2) void gemm_nt(
    const float* __restrict__ A, const float* __restrict__ B,
    float* __restrict__ C, int K, int N)
{
    const int coff = blockIdx.x * 128;
    gemm_core(A, B + (size_t)coff * K, C + coff, K, N, blockIdx.y * 128);
}

// ---------------------------------------------------------------------------
// RoPE (in place) on a [SEQ, H*128] row-major tensor.
// ---------------------------------------------------------------------------
__global__ __launch_bounds__(256) void rope_kernel(
    float* __restrict__ T, const float* __restrict__ cosT,
    const float* __restrict__ sinT, int H)
{
    int idx = blockIdx.x * blockDim.x + threadIdx.x;
    int total = SEQ * H * 64;
    if (idx >= total) return;
    int d = idx & 63;
    int h = (idx >> 6) % H;
    int s = idx / (64 * H);

    float* row = T + (size_t)s * (H * HD) + h * HD;
    float x1 = row[d];
    float x2 = row[d + 64];
    float c1 = cosT[s * HD + d],      s1 = sinT[s * HD + d];
    float c2 = cosT[s * HD + d + 64], s2 = sinT[s * HD + d + 64];
    row[d]      = fmaf(x1, c1, -x2 * s1);
    row[d + 64] = fmaf(x2, c2,  x1 * s2);
}

// ---------------------------------------------------------------------------
// Tensor-core flash attention, tf32 mma. Round 8: 256 threads / 8 warps,
// warp owns 16 q-rows; Q held in A-fragment REGISTERS (no Qs smem, no Q LDS);
// regs ~160 core (no spills); smem 101KB.
// ---------------------------------------------------------------------------
#define BQ   128
#define BKV  64
#define KS_  132
#define VS_  136
#define PS_  68

__global__ __launch_bounds__(256, 1) void attn_mma(
    const float* __restrict__ Q, const float* __restrict__ K,
    const float* __restrict__ V, float* __restrict__ ctx)
{
    const int qb  = gridDim.x - 1 - blockIdx.x;   // long rows first
    const int h   = blockIdx.y;
    const int hk  = h >> 2;
    const int tid = threadIdx.x;
    const int lane = tid & 31;
    const int warp = tid >> 5;     // 0..7
    const int gID  = lane >> 2;
    const int tig  = lane & 3;
    const int wrow = warp * 16;    // warp's q-row offset in the 128-row tile

    extern __shared__ float sm[];
    float* Ks = sm;                  // [64][132]
    float* Vs = Ks + BKV * KS_;      // [64][136]
    float* Ps = Vs + BKV * VS_;      // [128][68]

    const float scale = 0.08838834764831845f;  // 1/sqrt(128)

    // ---- Load Q A-fragments directly into registers (once) ----
    uint32_t qf[16][4];
    {
        const float* q0 = Q + (size_t)(qb * BQ + wrow + gID) * DOUT + h * HD;
        const float* q1 = q0 + (size_t)8 * DOUT;
#pragma unroll
        for (int ks = 0; ks < 16; ks++) {
            const int k = ks * 8;
            qf[ks][0] = __float_as_uint(f2tf32(q0[k + tig] * scale));
            qf[ks][1] = __float_as_uint(f2tf32(q1[k + tig] * scale));
            qf[ks][2] = __float_as_uint(f2tf32(q0[k + tig + 4] * scale));
            qf[ks][3] = __float_as_uint(f2tf32(q1[k + tig + 4] * scale));
        }
    }

    float mrow[2] = {-1e30f, -1e30f};
    float lrow[2] = {0.f, 0.f};
    float accO[16][4];
#pragma unroll
    for (int i = 0; i < 16; i++)
#pragma unroll
        for (int j = 0; j < 4; j++) accO[i][j] = 0.f;

    const int nkb = 2 * qb + 2;
    for (int kb = 0; kb < nkb; kb++) {
        __syncthreads();   // prev iter done reading Ks/Vs/Ps

        // Load K,V tiles (tf32): 64x128 each, 256 threads -> 32 floats each
        {
            const int r  = tid >> 2;
            const int cb = (tid & 3) * 32;
            const float* ksrc = K + (size_t)(kb * BKV + r) * (NKV * HD) + hk * HD + cb;
            const float* vsrc = V + (size_t)(kb * BKV + r) * (NKV * HD) + hk * HD + cb;
            float* kdst = Ks + r * KS_ + cb;
            float* vdst = Vs + r * VS_ + cb;
#pragma unroll
            for (int c = 0; c < 32; c += 4) {
                float4 k4 = *(const float4*)(ksrc + c);
                kdst[c + 0] = f2tf32(k4.x); kdst[c + 1] = f2tf32(k4.y);
                kdst[c + 2] = f2tf32(k4.z); kdst[c + 3] = f2tf32(k4.w);
                float4 v4 = *(const float4*)(vsrc + c);
                vdst[c + 0] = f2tf32(v4.x); vdst[c + 1] = f2tf32(v4.y);
                vdst[c + 2] = f2tf32(v4.z); vdst[c + 3] = f2tf32(v4.w);
            }
        }
        __syncthreads();

        // ---- S = Q @ K^T : warp computes 16x64 (Q from registers) ----
        float accS[8][4];
#pragma unroll
        for (int i = 0; i < 8; i++)
#pragma unroll
            for (int j = 0; j < 4; j++) accS[i][j] = 0.f;

        const uint32_t* Ku = (const uint32_t*)Ks;
#pragma unroll
        for (int ks = 0; ks < 16; ks++) {
            const int k = ks * 8;
#pragma unroll
            for (int nt = 0; nt < 8; nt++) {
                uint32_t b[2];
                b[0] = Ku[(nt * 8 + gID) * KS_ + k + tig];
                b[1] = Ku[(nt * 8 + gID) * KS_ + k + tig + 4];
                mma_tf32(accS[nt], qf[ks], b);
            }
        }

        // ---- causal mask (only tiles that can cross the diagonal) ----
        if (kb >= 2 * qb) {
            const int q0 = qb * BQ + wrow + gID;
            const int q1 = q0 + 8;
#pragma unroll
            for (int nt = 0; nt < 8; nt++) {
                const int kg = kb * BKV + nt * 8 + 2 * tig;
                if (kg > q0)     accS[nt][0] = -1e30f;
                if (kg + 1 > q0) accS[nt][1] = -1e30f;
                if (kg > q1)     accS[nt][2] = -1e30f;
                if (kg + 1 > q1) accS[nt][3] = -1e30f;
            }
        }

        // ---- online softmax ----
        float mx0 = -1e30f, mx1 = -1e30f;
#pragma unroll
        for (int nt = 0; nt < 8; nt++) {
            mx0 = fmaxf(mx0, fmaxf(accS[nt][0], accS[nt][1]));
            mx1 = fmaxf(mx1, fmaxf(accS[nt][2], accS[nt][3]));
        }
        mx0 = fmaxf(mx0, __shfl_xor_sync(0xffffffffu, mx0, 1));
        mx0 = fmaxf(mx0, __shfl_xor_sync(0xffffffffu, mx0, 2));
        mx1 = fmaxf(mx1, __shfl_xor_sync(0xffffffffu, mx1, 1));
        mx1 = fmaxf(mx1, __shfl_xor_sync(0xffffffffu, mx1, 2));

        float mn0 = fmaxf(mrow[0], mx0);
        float mn1 = fmaxf(mrow[1], mx1);
        float al0 = __expf(mrow[0] - mn0);
        float al1 = __expf(mrow[1] - mn1);
        mrow[0] = mn0; mrow[1] = mn1;

        float ls0 = 0.f, ls1 = 0.f;
        const int pr0 = wrow + gID;
#pragma unroll
        for (int nt = 0; nt < 8; nt++) {
            float p0 = __expf(accS[nt][0] - mn0);
            float p1 = __expf(accS[nt][1] - mn0);
            float p2 = __expf(accS[nt][2] - mn1);
            float p3 = __expf(accS[nt][3] - mn1);
            ls0 += p0 + p1;
            ls1 += p2 + p3;
            const int c = nt * 8 + 2 * tig;
            *(float2*)(Ps + pr0 * PS_ + c)       = make_float2(f2tf32(p0), f2tf32(p1));
            *(float2*)(Ps + (pr0 + 8) * PS_ + c) = make_float2(f2tf32(p2), f2tf32(p3));
        }
        ls0 += __shfl_xor_sync(0xffffffffu, ls0, 1);
        ls0 += __shfl_xor_sync(0xffffffffu, ls0, 2);
        ls1 += __shfl_xor_sync(0xffffffffu, ls1, 1);
        ls1 += __shfl_xor_sync(0xffffffffu, ls1, 2);
        lrow[0] = lrow[0] * al0 + ls0;
        lrow[1] = lrow[1] * al1 + ls1;

#pragma unroll
        for (int nt = 0; nt < 16; nt++) {
            accO[nt][0] *= al0; accO[nt][1] *= al0;
            accO[nt][2] *= al1; accO[nt][3] *= al1;
        }
        __syncwarp();   // Ps rows are warp-private

        // ---- O += P @ V : warp computes 16x128 ----
        const uint32_t* Pu = (const uint32_t*)Ps;
        const uint32_t* Vu = (const uint32_t*)Vs;
#pragma unroll
        for (int kt = 0; kt < 8; kt++) {
            const int k = kt * 8;
            uint32_t a[4];
            a[0] = Pu[pr0 * PS_ + k + tig];
            a[1] = Pu[(pr0 + 8) * PS_ + k + tig];
            a[2] = Pu[pr0 * PS_ + k + tig + 4];
            a[3] = Pu[(pr0 + 8) * PS_ + k + tig + 4];
#pragma unroll
            for (int nt = 0; nt < 16; nt++) {
                uint32_t b[2];
                b[0] = Vu[(k + tig)     * VS_ + nt * 8 + gID];
                b[1] = Vu[(k + tig + 4) * VS_ + nt * 8 + gID];
                mma_tf32(accO[nt], a, b);
            }
        }
    }

    // epilogue: normalize and store
    const float li0 = 1.f / lrow[0];
    const float li1 = 1.f / lrow[1];
    const int r0 = qb * BQ + wrow + gID;
    const int r1 = r0 + 8;
#pragma unroll
    for (int nt = 0; nt < 16; nt++) {
        const int c = h * HD + nt * 8 + 2 * tig;
        *(float2*)(ctx + (size_t)r0 * DOUT + c) =
            make_float2(accO[nt][0] * li0, accO[nt][1] * li0);
        *(float2*)(ctx + (size_t)r1 * DOUT + c) =
            make_float2(accO[nt][2] * li1, accO[nt][3] * li1);
    }
}

// ---------------------------------------------------------------------------
// Launch
// ---------------------------------------------------------------------------
extern "C" void kernel_launch(void* const* d_in, const int* in_sizes, int n_in,
                              void* d_out, int out_size)
{
    const float* x    = (const float*)d_in[0];
    const float* cosT = (const float*)d_in[1];
    const float* sinT = (const float*)d_in[2];
    const float* Wq   = (const float*)d_in[3];
    const float* Wk   = (const float*)d_in[4];
    const float* Wv   = (const float*)d_in[5];
    const float* Wo   = (const float*)d_in[6];
    float* out = (float*)d_out;

    float *Qp, *Kp, *Vp, *Cp;
    cudaGetSymbolAddress((void**)&Qp, g_Q);
    cudaGetSymbolAddress((void**)&Kp, g_K);
    cudaGetSymbolAddress((void**)&Vp, g_V);
    cudaGetSymbolAddress((void**)&Cp, g_ctx);

    cudaFuncSetAttribute(gemm_qkv, cudaFuncAttributeMaxDynamicSharedMemorySize, GEMM_SMEM);
    cudaFuncSetAttribute(gemm_nt,  cudaFuncAttributeMaxDynamicSharedMemorySize, GEMM_SMEM);

    const int ATTN_SMEM = (BKV * KS_ + BKV * VS_ + BQ * PS_) * (int)sizeof(float);
    cudaFuncSetAttribute(attn_mma, cudaFuncAttributeMaxDynamicSharedMemorySize, ATTN_SMEM);

    // Fused QKV projection
    gemm_qkv<<<dim3(48, SEQ / 128), 128, GEMM_SMEM>>>(x, Wq, Wk, Wv, Qp, Kp, Vp);

    // RoPE on Q and K
    {
        int totQ = SEQ * NH * 64;
        rope_kernel<<<(totQ + 255) / 256, 256>>>(Qp, cosT, sinT, NH);
        int totK = SEQ * NKV * 64;
        rope_kernel<<<(totK + 255) / 256, 256>>>(Kp, cosT, sinT, NKV);
    }

    // Tensor-core flash attention (BQ=128, 8 warps)
    attn_mma<<<dim3(SEQ / BQ, NH), 256, ATTN_SMEM>>>(Qp, Kp, Vp, Cp);

    // Output projection
    gemm_nt<<<dim3(DOUT / 128, SEQ / 128), 128, GEMM_SMEM>>>(Cp, Wo, out, DIN, DOUT);
}

// round 9
// speedup vs baseline: 1.0073x; 1.0073x over previous
#include <cuda_runtime.h>
#include <cuda_bf16.h>
#include <math.h>
#include <stdint.h>

// Problem constants
#define SEQ    2048
#define DIN    4096
#define DOUT   4096
#define NH     32
#define NKV    8
#define HD     128
#define GROUP  4

// Scratch buffers
__device__ float g_Q[SEQ * DOUT];
__device__ float g_K[SEQ * (NKV * HD)];
__device__ float g_V[SEQ * (NKV * HD)];
__device__ float g_ctx[SEQ * DOUT];

__device__ __forceinline__ float f2tf32(float x) {
    float r;
    asm("cvt.rna.tf32.f32 %0, %1;" : "=f"(r) : "f"(x));
    return r;
}

__device__ __forceinline__ uint32_t cvt_u(uint32_t u) {
    float f = __uint_as_float(u);
    asm("cvt.rna.tf32.f32 %0, %1;" : "=f"(f) : "f"(f));
    return __float_as_uint(f);
}

__device__ __forceinline__ void mma_tf32(float* c, const uint32_t* a, const uint32_t* b) {
    asm volatile(
        "mma.sync.aligned.m16n8k8.row.col.f32.tf32.tf32.f32 "
        "{%0,%1,%2,%3}, {%4,%5,%6,%7}, {%8,%9}, {%0,%1,%2,%3};"
        : "+f"(c[0]), "+f"(c[1]), "+f"(c[2]), "+f"(c[3])
        : "r"(a[0]), "r"(a[1]), "r"(a[2]), "r"(a[3]), "r"(b[0]), "r"(b[1]));
}

__device__ __forceinline__ uint32_t smem_u32(const void* p) {
    uint32_t a;
    asm("{ .reg .u64 t; cvta.to.shared.u64 t, %1; cvt.u32.u64 %0, t; }"
        : "=r"(a) : "l"(p));
    return a;
}

__device__ __forceinline__ void cp16(uint32_t dst, const float* src) {
    asm volatile("cp.async.cg.shared.global [%0], [%1], 16;"
                 :: "r"(dst), "l"(src) : "memory");
}
#define CP_COMMIT() asm volatile("cp.async.commit_group;" ::: "memory")
#define CP_WAIT(n)  asm volatile("cp.async.wait_group %0;" :: "n"(n) : "memory")

// ===========================================================================
// cp.async tf32 GEMM core (Round 5, + optional tf32-rounded output store)
// ===========================================================================
#define GS 3
#define STAGE_BYTES 32768
#define GEMM_SMEM (GS * STAGE_BYTES)

__device__ __forceinline__ void gemm_core(
    const float* __restrict__ A, const float* __restrict__ B,
    float* __restrict__ C, int K, int ldc, int bm, bool round_out)
{
    extern __shared__ char sbuf[];
    const uint32_t sbase = smem_u32(sbuf);
    const int tid  = threadIdx.x;
    const int lane = tid & 31;
    const int warp = tid >> 5;
    const int gID  = lane >> 2;
    const int tig  = lane & 3;
    const int wm   = (warp & 1) * 64;
    const int wn   = (warp >> 1) * 64;

    const int fr = tid >> 3;
    const int fc = tid & 7;

    float acc[4][8][4];
#pragma unroll
    for (int mi = 0; mi < 4; mi++)
#pragma unroll
        for (int ni = 0; ni < 8; ni++)
#pragma unroll
            for (int j = 0; j < 4; j++) acc[mi][ni][j] = 0.f;

    const int nK = K >> 5;

    auto fill = [&](int st, int kt) {
        const uint32_t dA = sbase + st * STAGE_BYTES;
        const uint32_t dB = dA + 16384;
        const float* gA = A + (size_t)bm * K + kt * 32;
        const float* gB = B + (size_t)kt * 32;
#pragma unroll
        for (int i = 0; i < 8; i++) {
            const int r = fr + i * 16;
            const uint32_t sw = (uint32_t)(r * 128 + ((fc ^ (r & 7)) * 16));
            cp16(dA + sw, gA + (size_t)r * K + fc * 4);
            cp16(dB + sw, gB + (size_t)r * K + fc * 4);
        }
    };

#pragma unroll
    for (int s = 0; s < GS - 1; s++) {
        if (s < nK) fill(s, s);
        CP_COMMIT();
    }

    for (int kt = 0; kt < nK; kt++) {
        const int nxt = kt + GS - 1;
        if (nxt < nK) fill(nxt % GS, nxt);
        CP_COMMIT();
        CP_WAIT(2);
        __syncthreads();

        const uint32_t* Sa = (const uint32_t*)(sbuf + (kt % GS) * STAGE_BYTES);
        const uint32_t* Sb = Sa + 4096;

#pragma unroll
        for (int kk = 0; kk < 4; kk++) {
            const int K4 = kk * 2;
            const int x0 = ((K4 ^ gID) * 4 + tig);
            const int x1 = (((K4 + 1) ^ gID) * 4 + tig);

            uint32_t af[4][4], bf[8][2];
#pragma unroll
            for (int mi = 0; mi < 4; mi++) {
                const int r = wm + mi * 16 + gID;
                af[mi][0] = cvt_u(Sa[r * 32 + x0]);
                af[mi][1] = cvt_u(Sa[(r + 8) * 32 + x0]);
                af[mi][2] = cvt_u(Sa[r * 32 + x1]);
                af[mi][3] = cvt_u(Sa[(r + 8) * 32 + x1]);
            }
#pragma unroll
            for (int ni = 0; ni < 8; ni++) {
                const int n = wn + ni * 8 + gID;
                bf[ni][0] = cvt_u(Sb[n * 32 + x0]);
                bf[ni][1] = cvt_u(Sb[n * 32 + x1]);
            }
#pragma unroll
            for (int mi = 0; mi < 4; mi++)
#pragma unroll
                for (int ni = 0; ni < 8; ni++)
                    mma_tf32(acc[mi][ni], af[mi], bf[ni]);
        }
        __syncthreads();
    }

#pragma unroll
    for (int mi = 0; mi < 4; mi++) {
        const int r0 = bm + wm + mi * 16 + gID;
#pragma unroll
        for (int ni = 0; ni < 8; ni++) {
            const int c0 = wn + ni * 8 + tig * 2;
            float* c = acc[mi][ni];
            if (round_out) {
                c[0] = f2tf32(c[0]); c[1] = f2tf32(c[1]);
                c[2] = f2tf32(c[2]); c[3] = f2tf32(c[3]);
            }
            *(float2*)(C + (size_t)r0 * ldc + c0)       = make_float2(c[0], c[1]);
            *(float2*)(C + (size_t)(r0 + 8) * ldc + c0) = make_float2(c[2], c[3]);
        }
    }
}

__global__ __launch_bounds__(128, 2) void gemm_qkv(
    const float* __restrict__ x,
    const float* __restrict__ Wq, const float* __restrict__ Wk,
    const float* __restrict__ Wv,
    float* __restrict__ Q, float* __restrict__ Ko, float* __restrict__ Vo)
{
    const int bn = blockIdx.x;
    const int bm = blockIdx.y * 128;
    const float* B;
    float* C;
    int ldc, coff;
    bool ro = false;
    if (bn < 32)      { B = Wq; C = Q;  ldc = DOUT; coff = bn * 128; }
    else if (bn < 40) { B = Wk; C = Ko; ldc = NKV * HD; coff = (bn - 32) * 128; }
    else              { B = Wv; C = Vo; ldc = NKV * HD; coff = (bn - 40) * 128; ro = true; }
    gemm_core(x, B + (size_t)coff * DIN, C + coff, DIN, ldc, bm, ro);
}

__global__ __launch_bounds__(128, 2) void gemm_nt(
    const float* __restrict__ A, const float* __restrict__ B,
    float* __restrict__ C, int K, int N)
{
    const int coff = blockIdx.x * 128;
    gemm_core(A, B + (size_t)coff * K, C + coff, K, N, blockIdx.y * 128, false);
}

// ---------------------------------------------------------------------------
// RoPE (in place); optional tf32 rounding of the result (used for K).
// ---------------------------------------------------------------------------
__global__ __launch_bounds__(256) void rope_kernel(
    float* __restrict__ T, const float* __restrict__ cosT,
    const float* __restrict__ sinT, int H, int round_out)
{
    int idx = blockIdx.x * blockDim.x + threadIdx.x;
    int total = SEQ * H * 64;
    if (idx >= total) return;
    int d = idx & 63;
    int h = (idx >> 6) % H;
    int s = idx / (64 * H);

    float* row = T + (size_t)s * (H * HD) + h * HD;
    float x1 = row[d];
    float x2 = row[d + 64];
    float c1 = cosT[s * HD + d],      s1 = sinT[s * HD + d];
    float c2 = cosT[s * HD + d + 64], s2 = sinT[s * HD + d + 64];
    float o1 = fmaf(x1, c1, -x2 * s1);
    float o2 = fmaf(x2, c2,  x1 * s2);
    if (round_out) { o1 = f2tf32(o1); o2 = f2tf32(o2); }
    row[d]      = o1;
    row[d + 64] = o2;
}

// ---------------------------------------------------------------------------
// Tensor-core flash attention. Round 9: K/V pre-rounded to tf32 in memory;
// fills are pure cp.async into a DOUBLE-BUFFERED XOR-swizzled smem layout
// (prefetch tile kb+1 during compute of kb). Q in registers (R8).
// K/V stage layout: row r = 128 floats (512B, 32 chunks of 16B);
//   chunk c stored at r*512 + ((c ^ (r&7))<<4).
// ---------------------------------------------------------------------------
#define BQ   128
#define BKV  64
#define PS_  68
#define ATT_STAGE 65536   // K tile 32KB + V tile 32KB
#define ATT_SMEM  (2 * ATT_STAGE + BQ * PS_ * 4)

__global__ __launch_bounds__(256, 1) void attn_mma(
    const float* __restrict__ Q, const float* __restrict__ K,
    const float* __restrict__ V, float* __restrict__ ctx)
{
    const int qb  = gridDim.x - 1 - blockIdx.x;   // long rows first
    const int h   = blockIdx.y;
    const int hk  = h >> 2;
    const int tid = threadIdx.x;
    const int lane = tid & 31;
    const int warp = tid >> 5;
    const int gID  = lane >> 2;
    const int tig  = lane & 3;
    const int wrow = warp * 16;

    extern __shared__ char smc[];
    const uint32_t sbase = smem_u32(smc);
    float* Ps = (float*)(smc + 2 * ATT_STAGE);

    const float scale = 0.08838834764831845f;  // 1/sqrt(128)

    // ---- cp.async fill of one stage (K 32KB + V 32KB) ----
    auto fill = [&](int buf, int kb) {
        const int r  = tid >> 2;             // 0..63
        const int bc = (tid & 3) * 8;        // chunk base 0,8,16,24
        const uint32_t kdst = sbase + buf * ATT_STAGE + r * 512;
        const uint32_t vdst = kdst + 32768;
        const float* ksrc = K + (size_t)(kb * BKV + r) * (NKV * HD) + hk * HD;
        const float* vsrc = V + (size_t)(kb * BKV + r) * (NKV * HD) + hk * HD;
#pragma unroll
        for (int j = 0; j < 8; j++) {
            const int ch = bc + j;
            const uint32_t sw = (uint32_t)((ch ^ (r & 7)) << 4);
            cp16(kdst + sw, ksrc + ch * 4);
            cp16(vdst + sw, vsrc + ch * 4);
        }
    };

    // ---- Load Q A-fragments into registers (raw fp32 -> scaled tf32) ----
    uint32_t qf[16][4];
    {
        const float* q0 = Q + (size_t)(qb * BQ + wrow + gID) * DOUT + h * HD;
        const float* q1 = q0 + (size_t)8 * DOUT;
#pragma unroll
        for (int ks = 0; ks < 16; ks++) {
            const int k = ks * 8;
            qf[ks][0] = __float_as_uint(f2tf32(q0[k + tig] * scale));
            qf[ks][1] = __float_as_uint(f2tf32(q1[k + tig] * scale));
            qf[ks][2] = __float_as_uint(f2tf32(q0[k + tig + 4] * scale));
            qf[ks][3] = __float_as_uint(f2tf32(q1[k + tig + 4] * scale));
        }
    }

    float mrow[2] = {-1e30f, -1e30f};
    float lrow[2] = {0.f, 0.f};
    float accO[16][4];
#pragma unroll
    for (int i = 0; i < 16; i++)
#pragma unroll
        for (int j = 0; j < 4; j++) accO[i][j] = 0.f;

    const int nkb = 2 * qb + 2;

    // prologue: prefetch tile 0
    fill(0, 0);
    CP_COMMIT();

    for (int kb = 0; kb < nkb; kb++) {
        const int buf = kb & 1;
        if (kb + 1 < nkb) fill((kb + 1) & 1, kb + 1);
        CP_COMMIT();
        CP_WAIT(1);          // stage kb complete (in-order group retirement)
        __syncthreads();

        const uint32_t* Ku = (const uint32_t*)(smc + buf * ATT_STAGE);
        const uint32_t* Vu = Ku + 8192;

        // ---- S = Q @ K^T : warp computes 16x64 ----
        float accS[8][4];
#pragma unroll
        for (int i = 0; i < 8; i++)
#pragma unroll
            for (int j = 0; j < 4; j++) accS[i][j] = 0.f;

#pragma unroll
        for (int ks = 0; ks < 16; ks++) {
            const int k4 = ks * 2;     // 16B-chunk index of k..k+3
#pragma unroll
            for (int nt = 0; nt < 8; nt++) {
                const int row = nt * 8 + gID;
                const int rx  = row & 7;
                uint32_t b[2];
                b[0] = Ku[row * 128 + ((k4 ^ rx) << 2) + tig];
                b[1] = Ku[row * 128 + (((k4 + 1) ^ rx) << 2) + tig];
                mma_tf32(accS[nt], qf[ks], b);
            }
        }

        // ---- causal mask (only tiles crossing the diagonal) ----
        if (kb >= 2 * qb) {
            const int q0 = qb * BQ + wrow + gID;
            const int q1 = q0 + 8;
#pragma unroll
            for (int nt = 0; nt < 8; nt++) {
                const int kg = kb * BKV + nt * 8 + 2 * tig;
                if (kg > q0)     accS[nt][0] = -1e30f;
                if (kg + 1 > q0) accS[nt][1] = -1e30f;
                if (kg > q1)     accS[nt][2] = -1e30f;
                if (kg + 1 > q1) accS[nt][3] = -1e30f;
            }
        }

        // ---- online softmax ----
        float mx0 = -1e30f, mx1 = -1e30f;
#pragma unroll
        for (int nt = 0; nt < 8; nt++) {
            mx0 = fmaxf(mx0, fmaxf(accS[nt][0], accS[nt][1]));
            mx1 = fmaxf(mx1, fmaxf(accS[nt][2], accS[nt][3]));
        }
        mx0 = fmaxf(mx0, __shfl_xor_sync(0xffffffffu, mx0, 1));
        mx0 = fmaxf(mx0, __shfl_xor_sync(0xffffffffu, mx0, 2));
        mx1 = fmaxf(mx1, __shfl_xor_sync(0xffffffffu, mx1, 1));
        mx1 = fmaxf(mx1, __shfl_xor_sync(0xffffffffu, mx1, 2));

        float mn0 = fmaxf(mrow[0], mx0);
        float mn1 = fmaxf(mrow[1], mx1);
        float al0 = __expf(mrow[0] - mn0);
        float al1 = __expf(mrow[1] - mn1);
        mrow[0] = mn0; mrow[1] = mn1;

        float ls0 = 0.f, ls1 = 0.f;
        const int pr0 = wrow + gID;
#pragma unroll
        for (int nt = 0; nt < 8; nt++) {
            float p0 = __expf(accS[nt][0] - mn0);
            float p1 = __expf(accS[nt][1] - mn0);
            float p2 = __expf(accS[nt][2] - mn1);
            float p3 = __expf(accS[nt][3] - mn1);
            ls0 += p0 + p1;
            ls1 += p2 + p3;
            const int c = nt * 8 + 2 * tig;
            *(float2*)(Ps + pr0 * PS_ + c)       = make_float2(f2tf32(p0), f2tf32(p1));
            *(float2*)(Ps + (pr0 + 8) * PS_ + c) = make_float2(f2tf32(p2), f2tf32(p3));
        }
        ls0 += __shfl_xor_sync(0xffffffffu, ls0, 1);
        ls0 += __shfl_xor_sync(0xffffffffu, ls0, 2);
        ls1 += __shfl_xor_sync(0xffffffffu, ls1, 1);
        ls1 += __shfl_xor_sync(0xffffffffu, ls1, 2);
        lrow[0] = lrow[0] * al0 + ls0;
        lrow[1] = lrow[1] * al1 + ls1;

#pragma unroll
        for (int nt = 0; nt < 16; nt++) {
            accO[nt][0] *= al0; accO[nt][1] *= al0;
            accO[nt][2] *= al1; accO[nt][3] *= al1;
        }
        __syncwarp();   // Ps rows are warp-private

        // ---- O += P @ V : warp computes 16x128 ----
        const uint32_t* Pu = (const uint32_t*)Ps;
#pragma unroll
        for (int kt = 0; kt < 8; kt++) {
            const int k = kt * 8;
            uint32_t a[4];
            a[0] = Pu[pr0 * PS_ + k + tig];
            a[1] = Pu[(pr0 + 8) * PS_ + k + tig];
            a[2] = Pu[pr0 * PS_ + k + tig + 4];
            a[3] = Pu[(pr0 + 8) * PS_ + k + tig + 4];
            const int row0 = k + tig;        // row0 & 7 == tig
            const int row1 = k + tig + 4;    // row1 & 7 == tig + 4
#pragma unroll
            for (int nt = 0; nt < 16; nt++) {
                const int ch = 2 * nt + (gID >> 2);
                uint32_t b[2];
                b[0] = Vu[row0 * 128 + ((ch ^ tig) << 2) + (gID & 3)];
                b[1] = Vu[row1 * 128 + ((ch ^ (tig + 4)) << 2) + (gID & 3)];
                mma_tf32(accO[nt], a, b);
            }
        }
        __syncthreads();   // done reading buf before next-next fill overwrites
    }

    // epilogue: normalize and store
    const float li0 = 1.f / lrow[0];
    const float li1 = 1.f / lrow[1];
    const int r0 = qb * BQ + wrow + gID;
    const int r1 = r0 + 8;
#pragma unroll
    for (int nt = 0; nt < 16; nt++) {
        const int c = h * HD + nt * 8 + 2 * tig;
        *(float2*)(ctx + (size_t)r0 * DOUT + c) =
            make_float2(accO[nt][0] * li0, accO[nt][1] * li0);
        *(float2*)(ctx + (size_t)r1 * DOUT + c) =
            make_float2(accO[nt][2] * li1, accO[nt][3] * li1);
    }
}

// ---------------------------------------------------------------------------
// Launch
// ---------------------------------------------------------------------------
extern "C" void kernel_launch(void* const* d_in, const int* in_sizes, int n_in,
                              void* d_out, int out_size)
{
    const float* x    = (const float*)d_in[0];
    const float* cosT = (const float*)d_in[1];
    const float* sinT = (const float*)d_in[2];
    const float* Wq   = (const float*)d_in[3];
    const float* Wk   = (const float*)d_in[4];
    const float* Wv   = (const float*)d_in[5];
    const float* Wo   = (const float*)d_in[6];
    float* out = (float*)d_out;

    float *Qp, *Kp, *Vp, *Cp;
    cudaGetSymbolAddress((void**)&Qp, g_Q);
    cudaGetSymbolAddress((void**)&Kp, g_K);
    cudaGetSymbolAddress((void**)&Vp, g_V);
    cudaGetSymbolAddress((void**)&Cp, g_ctx);

    cudaFuncSetAttribute(gemm_qkv, cudaFuncAttributeMaxDynamicSharedMemorySize, GEMM_SMEM);
    cudaFuncSetAttribute(gemm_nt,  cudaFuncAttributeMaxDynamicSharedMemorySize, GEMM_SMEM);
    cudaFuncSetAttribute(attn_mma, cudaFuncAttributeMaxDynamicSharedMemorySize, ATT_SMEM);

    // Fused QKV projection (V written tf32-rounded)
    gemm_qkv<<<dim3(48, SEQ / 128), 128, GEMM_SMEM>>>(x, Wq, Wk, Wv, Qp, Kp, Vp);

    // RoPE: Q raw, K tf32-rounded on write
    {
        int totQ = SEQ * NH * 64;
        rope_kernel<<<(totQ + 255) / 256, 256>>>(Qp, cosT, sinT, NH, 0);
        int totK = SEQ * NKV * 64;
        rope_kernel<<<(totK + 255) / 256, 256>>>(Kp, cosT, sinT, NKV, 1);
    }

    // Tensor-core flash attention (cp.async double-buffered K/V)
    attn_mma<<<dim3(SEQ / BQ, NH), 256, ATT_SMEM>>>(Qp, Kp, Vp, Cp);

    // Output projection
    gemm_nt<<<dim3(DOUT / 128, SEQ / 128), 128, GEMM_SMEM>>>(Cp, Wo, out, DIN, DOUT);
}

// round 10
// speedup vs baseline: 1.0122x; 1.0049x over previous
#include <cuda_runtime.h>
#include <cuda_bf16.h>
#include <math.h>
#include <stdint.h>

// Problem constants
#define SEQ    2048
#define DIN    4096
#define DOUT   4096
#define NH     32
#define NKV    8
#define HD     128
#define GROUP  4

// Scratch buffers
__device__ float g_Q[SEQ * DOUT];
__device__ float g_K[SEQ * (NKV * HD)];
__device__ float g_V[SEQ * (NKV * HD)];
__device__ float g_ctx[SEQ * DOUT];
// tf32-pre-rounded operands
__device__ float g_xr[SEQ * DIN];
__device__ float g_Wqr[DOUT * DIN];
__device__ float g_Wkr[(NKV * HD) * DIN];
__device__ float g_Wvr[(NKV * HD) * DIN];
__device__ float g_Wor[DOUT * DOUT];

__device__ __forceinline__ float f2tf32(float x) {
    float r;
    asm("cvt.rna.tf32.f32 %0, %1;" : "=f"(r) : "f"(x));
    return r;
}

__device__ __forceinline__ void mma_tf32(float* c, const uint32_t* a, const uint32_t* b) {
    asm volatile(
        "mma.sync.aligned.m16n8k8.row.col.f32.tf32.tf32.f32 "
        "{%0,%1,%2,%3}, {%4,%5,%6,%7}, {%8,%9}, {%0,%1,%2,%3};"
        : "+f"(c[0]), "+f"(c[1]), "+f"(c[2]), "+f"(c[3])
        : "r"(a[0]), "r"(a[1]), "r"(a[2]), "r"(a[3]), "r"(b[0]), "r"(b[1]));
}

__device__ __forceinline__ uint32_t smem_u32(const void* p) {
    uint32_t a;
    asm("{ .reg .u64 t; cvta.to.shared.u64 t, %1; cvt.u32.u64 %0, t; }"
        : "=r"(a) : "l"(p));
    return a;
}

__device__ __forceinline__ void cp16(uint32_t dst, const float* src) {
    asm volatile("cp.async.cg.shared.global [%0], [%1], 16;"
                 :: "r"(dst), "l"(src) : "memory");
}
#define CP_COMMIT() asm volatile("cp.async.commit_group;" ::: "memory")
#define CP_WAIT(n)  asm volatile("cp.async.wait_group %0;" :: "n"(n) : "memory")

// ---------------------------------------------------------------------------
// Elementwise tf32 pre-rounding (grid-stride, float4)
// ---------------------------------------------------------------------------
__global__ __launch_bounds__(256) void round_tf32(
    const float* __restrict__ in, float* __restrict__ out, int n4)
{
    for (int i = blockIdx.x * blockDim.x + threadIdx.x; i < n4;
         i += gridDim.x * blockDim.x) {
        float4 v = *(const float4*)(in + (size_t)i * 4);
        v.x = f2tf32(v.x); v.y = f2tf32(v.y);
        v.z = f2tf32(v.z); v.w = f2tf32(v.w);
        *(float4*)(out + (size_t)i * 4) = v;
    }
}

// ===========================================================================
// cp.async tf32 GEMM core — inputs are PRE-ROUNDED tf32; no cvt in mainloop.
// ===========================================================================
#define GS 3
#define STAGE_BYTES 32768
#define GEMM_SMEM (GS * STAGE_BYTES)

__device__ __forceinline__ void gemm_core(
    const float* __restrict__ A, const float* __restrict__ B,
    float* __restrict__ C, int K, int ldc, int bm, bool round_out)
{
    extern __shared__ char sbuf[];
    const uint32_t sbase = smem_u32(sbuf);
    const int tid  = threadIdx.x;
    const int lane = tid & 31;
    const int warp = tid >> 5;
    const int gID  = lane >> 2;
    const int tig  = lane & 3;
    const int wm   = (warp & 1) * 64;
    const int wn   = (warp >> 1) * 64;

    const int fr = tid >> 3;
    const int fc = tid & 7;

    float acc[4][8][4];
#pragma unroll
    for (int mi = 0; mi < 4; mi++)
#pragma unroll
        for (int ni = 0; ni < 8; ni++)
#pragma unroll
            for (int j = 0; j < 4; j++) acc[mi][ni][j] = 0.f;

    const int nK = K >> 5;

    auto fill = [&](int st, int kt) {
        const uint32_t dA = sbase + st * STAGE_BYTES;
        const uint32_t dB = dA + 16384;
        const float* gA = A + (size_t)bm * K + kt * 32;
        const float* gB = B + (size_t)kt * 32;
#pragma unroll
        for (int i = 0; i < 8; i++) {
            const int r = fr + i * 16;
            const uint32_t sw = (uint32_t)(r * 128 + ((fc ^ (r & 7)) * 16));
            cp16(dA + sw, gA + (size_t)r * K + fc * 4);
            cp16(dB + sw, gB + (size_t)r * K + fc * 4);
        }
    };

#pragma unroll
    for (int s = 0; s < GS - 1; s++) {
        if (s < nK) fill(s, s);
        CP_COMMIT();
    }

    for (int kt = 0; kt < nK; kt++) {
        const int nxt = kt + GS - 1;
        if (nxt < nK) fill(nxt % GS, nxt);
        CP_COMMIT();
        CP_WAIT(2);
        __syncthreads();

        const uint32_t* Sa = (const uint32_t*)(sbuf + (kt % GS) * STAGE_BYTES);
        const uint32_t* Sb = Sa + 4096;

#pragma unroll
        for (int kk = 0; kk < 4; kk++) {
            const int K4 = kk * 2;
            const int x0 = ((K4 ^ gID) * 4 + tig);
            const int x1 = (((K4 + 1) ^ gID) * 4 + tig);

            uint32_t af[4][4], bf[8][2];
#pragma unroll
            for (int mi = 0; mi < 4; mi++) {
                const int r = wm + mi * 16 + gID;
                af[mi][0] = Sa[r * 32 + x0];
                af[mi][1] = Sa[(r + 8) * 32 + x0];
                af[mi][2] = Sa[r * 32 + x1];
                af[mi][3] = Sa[(r + 8) * 32 + x1];
            }
#pragma unroll
            for (int ni = 0; ni < 8; ni++) {
                const int n = wn + ni * 8 + gID;
                bf[ni][0] = Sb[n * 32 + x0];
                bf[ni][1] = Sb[n * 32 + x1];
            }
#pragma unroll
            for (int mi = 0; mi < 4; mi++)
#pragma unroll
                for (int ni = 0; ni < 8; ni++)
                    mma_tf32(acc[mi][ni], af[mi], bf[ni]);
        }
        __syncthreads();
    }

#pragma unroll
    for (int mi = 0; mi < 4; mi++) {
        const int r0 = bm + wm + mi * 16 + gID;
#pragma unroll
        for (int ni = 0; ni < 8; ni++) {
            const int c0 = wn + ni * 8 + tig * 2;
            float* c = acc[mi][ni];
            if (round_out) {
                c[0] = f2tf32(c[0]); c[1] = f2tf32(c[1]);
                c[2] = f2tf32(c[2]); c[3] = f2tf32(c[3]);
            }
            *(float2*)(C + (size_t)r0 * ldc + c0)       = make_float2(c[0], c[1]);
            *(float2*)(C + (size_t)(r0 + 8) * ldc + c0) = make_float2(c[2], c[3]);
        }
    }
}

__global__ __launch_bounds__(128, 2) void gemm_qkv(
    const float* __restrict__ x,
    const float* __restrict__ Wq, const float* __restrict__ Wk,
    const float* __restrict__ Wv,
    float* __restrict__ Q, float* __restrict__ Ko, float* __restrict__ Vo)
{
    const int bn = blockIdx.x;
    const int bm = blockIdx.y * 128;
    const float* B;
    float* C;
    int ldc, coff;
    bool ro = false;
    if (bn < 32)      { B = Wq; C = Q;  ldc = DOUT; coff = bn * 128; }
    else if (bn < 40) { B = Wk; C = Ko; ldc = NKV * HD; coff = (bn - 32) * 128; }
    else              { B = Wv; C = Vo; ldc = NKV * HD; coff = (bn - 40) * 128; ro = true; }
    gemm_core(x, B + (size_t)coff * DIN, C + coff, DIN, ldc, bm, ro);
}

__global__ __launch_bounds__(128, 2) void gemm_nt(
    const float* __restrict__ A, const float* __restrict__ B,
    float* __restrict__ C, int K, int N)
{
    const int coff = blockIdx.x * 128;
    gemm_core(A, B + (size_t)coff * K, C + coff, K, N, blockIdx.y * 128, false);
}

// ---------------------------------------------------------------------------
// RoPE (in place); optional tf32 rounding of the result (used for K).
// ---------------------------------------------------------------------------
__global__ __launch_bounds__(256) void rope_kernel(
    float* __restrict__ T, const float* __restrict__ cosT,
    const float* __restrict__ sinT, int H, int round_out)
{
    int idx = blockIdx.x * blockDim.x + threadIdx.x;
    int total = SEQ * H * 64;
    if (idx >= total) return;
    int d = idx & 63;
    int h = (idx >> 6) % H;
    int s = idx / (64 * H);

    float* row = T + (size_t)s * (H * HD) + h * HD;
    float x1 = row[d];
    float x2 = row[d + 64];
    float c1 = cosT[s * HD + d],      s1 = sinT[s * HD + d];
    float c2 = cosT[s * HD + d + 64], s2 = sinT[s * HD + d + 64];
    float o1 = fmaf(x1, c1, -x2 * s1);
    float o2 = fmaf(x2, c2,  x1 * s2);
    if (round_out) { o1 = f2tf32(o1); o2 = f2tf32(o2); }
    row[d]      = o1;
    row[d + 64] = o2;
}

// ---------------------------------------------------------------------------
// Tensor-core flash attention (unchanged from Round 9, except ctx is stored
// tf32-rounded so the O-projection needs no cvt).
// ---------------------------------------------------------------------------
#define BQ   128
#define BKV  64
#define PS_  68
#define ATT_STAGE 65536
#define ATT_SMEM  (2 * ATT_STAGE + BQ * PS_ * 4)

__global__ __launch_bounds__(256, 1) void attn_mma(
    const float* __restrict__ Q, const float* __restrict__ K,
    const float* __restrict__ V, float* __restrict__ ctx)
{
    const int qb  = gridDim.x - 1 - blockIdx.x;
    const int h   = blockIdx.y;
    const int hk  = h >> 2;
    const int tid = threadIdx.x;
    const int lane = tid & 31;
    const int warp = tid >> 5;
    const int gID  = lane >> 2;
    const int tig  = lane & 3;
    const int wrow = warp * 16;

    extern __shared__ char smc[];
    const uint32_t sbase = smem_u32(smc);
    float* Ps = (float*)(smc + 2 * ATT_STAGE);

    const float scale = 0.08838834764831845f;

    auto fill = [&](int buf, int kb) {
        const int r  = tid >> 2;
        const int bc = (tid & 3) * 8;
        const uint32_t kdst = sbase + buf * ATT_STAGE + r * 512;
        const uint32_t vdst = kdst + 32768;
        const float* ksrc = K + (size_t)(kb * BKV + r) * (NKV * HD) + hk * HD;
        const float* vsrc = V + (size_t)(kb * BKV + r) * (NKV * HD) + hk * HD;
#pragma unroll
        for (int j = 0; j < 8; j++) {
            const int ch = bc + j;
            const uint32_t sw = (uint32_t)((ch ^ (r & 7)) << 4);
            cp16(kdst + sw, ksrc + ch * 4);
            cp16(vdst + sw, vsrc + ch * 4);
        }
    };

    uint32_t qf[16][4];
    {
        const float* q0 = Q + (size_t)(qb * BQ + wrow + gID) * DOUT + h * HD;
        const float* q1 = q0 + (size_t)8 * DOUT;
#pragma unroll
        for (int ks = 0; ks < 16; ks++) {
            const int k = ks * 8;
            qf[ks][0] = __float_as_uint(f2tf32(q0[k + tig] * scale));
            qf[ks][1] = __float_as_uint(f2tf32(q1[k + tig] * scale));
            qf[ks][2] = __float_as_uint(f2tf32(q0[k + tig + 4] * scale));
            qf[ks][3] = __float_as_uint(f2tf32(q1[k + tig + 4] * scale));
        }
    }

    float mrow[2] = {-1e30f, -1e30f};
    float lrow[2] = {0.f, 0.f};
    float accO[16][4];
#pragma unroll
    for (int i = 0; i < 16; i++)
#pragma unroll
        for (int j = 0; j < 4; j++) accO[i][j] = 0.f;

    const int nkb = 2 * qb + 2;

    fill(0, 0);
    CP_COMMIT();

    for (int kb = 0; kb < nkb; kb++) {
        const int buf = kb & 1;
        if (kb + 1 < nkb) fill((kb + 1) & 1, kb + 1);
        CP_COMMIT();
        CP_WAIT(1);
        __syncthreads();

        const uint32_t* Ku = (const uint32_t*)(smc + buf * ATT_STAGE);
        const uint32_t* Vu = Ku + 8192;

        float accS[8][4];
#pragma unroll
        for (int i = 0; i < 8; i++)
#pragma unroll
            for (int j = 0; j < 4; j++) accS[i][j] = 0.f;

#pragma unroll
        for (int ks = 0; ks < 16; ks++) {
            const int k4 = ks * 2;
#pragma unroll
            for (int nt = 0; nt < 8; nt++) {
                const int row = nt * 8 + gID;
                const int rx  = row & 7;
                uint32_t b[2];
                b[0] = Ku[row * 128 + ((k4 ^ rx) << 2) + tig];
                b[1] = Ku[row * 128 + (((k4 + 1) ^ rx) << 2) + tig];
                mma_tf32(accS[nt], qf[ks], b);
            }
        }

        if (kb >= 2 * qb) {
            const int q0 = qb * BQ + wrow + gID;
            const int q1 = q0 + 8;
#pragma unroll
            for (int nt = 0; nt < 8; nt++) {
                const int kg = kb * BKV + nt * 8 + 2 * tig;
                if (kg > q0)     accS[nt][0] = -1e30f;
                if (kg + 1 > q0) accS[nt][1] = -1e30f;
                if (kg > q1)     accS[nt][2] = -1e30f;
                if (kg + 1 > q1) accS[nt][3] = -1e30f;
            }
        }

        float mx0 = -1e30f, mx1 = -1e30f;
#pragma unroll
        for (int nt = 0; nt < 8; nt++) {
            mx0 = fmaxf(mx0, fmaxf(accS[nt][0], accS[nt][1]));
            mx1 = fmaxf(mx1, fmaxf(accS[nt][2], accS[nt][3]));
        }
        mx0 = fmaxf(mx0, __shfl_xor_sync(0xffffffffu, mx0, 1));
        mx0 = fmaxf(mx0, __shfl_xor_sync(0xffffffffu, mx0, 2));
        mx1 = fmaxf(mx1, __shfl_xor_sync(0xffffffffu, mx1, 1));
        mx1 = fmaxf(mx1, __shfl_xor_sync(0xffffffffu, mx1, 2));

        float mn0 = fmaxf(mrow[0], mx0);
        float mn1 = fmaxf(mrow[1], mx1);
        float al0 = __expf(mrow[0] - mn0);
        float al1 = __expf(mrow[1] - mn1);
        mrow[0] = mn0; mrow[1] = mn1;

        float ls0 = 0.f, ls1 = 0.f;
        const int pr0 = wrow + gID;
#pragma unroll
        for (int nt = 0; nt < 8; nt++) {
            float p0 = __expf(accS[nt][0] - mn0);
            float p1 = __expf(accS[nt][1] - mn0);
            float p2 = __expf(accS[nt][2] - mn1);
            float p3 = __expf(accS[nt][3] - mn1);
            ls0 += p0 + p1;
            ls1 += p2 + p3;
            const int c = nt * 8 + 2 * tig;
            *(float2*)(Ps + pr0 * PS_ + c)       = make_float2(f2tf32(p0), f2tf32(p1));
            *(float2*)(Ps + (pr0 + 8) * PS_ + c) = make_float2(f2tf32(p2), f2tf32(p3));
        }
        ls0 += __shfl_xor_sync(0xffffffffu, ls0, 1);
        ls0 += __shfl_xor_sync(0xffffffffu, ls0, 2);
        ls1 += __shfl_xor_sync(0xffffffffu, ls1, 1);
        ls1 += __shfl_xor_sync(0xffffffffu, ls1, 2);
        lrow[0] = lrow[0] * al0 + ls0;
        lrow[1] = lrow[1] * al1 + ls1;

#pragma unroll
        for (int nt = 0; nt < 16; nt++) {
            accO[nt][0] *= al0; accO[nt][1] *= al0;
            accO[nt][2] *= al1; accO[nt][3] *= al1;
        }
        __syncwarp();

        const uint32_t* Pu = (const uint32_t*)Ps;
#pragma unroll
        for (int kt = 0; kt < 8; kt++) {
            const int k = kt * 8;
            uint32_t a[4];
            a[0] = Pu[pr0 * PS_ + k + tig];
            a[1] = Pu[(pr0 + 8) * PS_ + k + tig];
            a[2] = Pu[pr0 * PS_ + k + tig + 4];
            a[3] = Pu[(pr0 + 8) * PS_ + k + tig + 4];
            const int row0 = k + tig;
            const int row1 = k + tig + 4;
#pragma unroll
            for (int nt = 0; nt < 16; nt++) {
                const int ch = 2 * nt + (gID >> 2);
                uint32_t b[2];
                b[0] = Vu[row0 * 128 + ((ch ^ tig) << 2) + (gID & 3)];
                b[1] = Vu[row1 * 128 + ((ch ^ (tig + 4)) << 2) + (gID & 3)];
                mma_tf32(accO[nt], a, b);
            }
        }
        __syncthreads();
    }

    // epilogue: normalize, round to tf32 (feeds O-projection pre-rounded)
    const float li0 = 1.f / lrow[0];
    const float li1 = 1.f / lrow[1];
    const int r0 = qb * BQ + wrow + gID;
    const int r1 = r0 + 8;
#pragma unroll
    for (int nt = 0; nt < 16; nt++) {
        const int c = h * HD + nt * 8 + 2 * tig;
        *(float2*)(ctx + (size_t)r0 * DOUT + c) =
            make_float2(f2tf32(accO[nt][0] * li0), f2tf32(accO[nt][1] * li0));
        *(float2*)(ctx + (size_t)r1 * DOUT + c) =
            make_float2(f2tf32(accO[nt][2] * li1), f2tf32(accO[nt][3] * li1));
    }
}

// ---------------------------------------------------------------------------
// Launch
// ---------------------------------------------------------------------------
extern "C" void kernel_launch(void* const* d_in, const int* in_sizes, int n_in,
                              void* d_out, int out_size)
{
    const float* x    = (const float*)d_in[0];
    const float* cosT = (const float*)d_in[1];
    const float* sinT = (const float*)d_in[2];
    const float* Wq   = (const float*)d_in[3];
    const float* Wk   = (const float*)d_in[4];
    const float* Wv   = (const float*)d_in[5];
    const float* Wo   = (const float*)d_in[6];
    float* out = (float*)d_out;

    float *Qp, *Kp, *Vp, *Cp, *xr, *Wqr, *Wkr, *Wvr, *Wor;
    cudaGetSymbolAddress((void**)&Qp, g_Q);
    cudaGetSymbolAddress((void**)&Kp, g_K);
    cudaGetSymbolAddress((void**)&Vp, g_V);
    cudaGetSymbolAddress((void**)&Cp, g_ctx);
    cudaGetSymbolAddress((void**)&xr, g_xr);
    cudaGetSymbolAddress((void**)&Wqr, g_Wqr);
    cudaGetSymbolAddress((void**)&Wkr, g_Wkr);
    cudaGetSymbolAddress((void**)&Wvr, g_Wvr);
    cudaGetSymbolAddress((void**)&Wor, g_Wor);

    cudaFuncSetAttribute(gemm_qkv, cudaFuncAttributeMaxDynamicSharedMemorySize, GEMM_SMEM);
    cudaFuncSetAttribute(gemm_nt,  cudaFuncAttributeMaxDynamicSharedMemorySize, GEMM_SMEM);
    cudaFuncSetAttribute(attn_mma, cudaFuncAttributeMaxDynamicSharedMemorySize, ATT_SMEM);

    // Pre-round GEMM operands to tf32 (bit-identical to per-fragment cvt)
    round_tf32<<<2048, 256>>>(x,  xr,  (SEQ * DIN) / 4);
    round_tf32<<<2048, 256>>>(Wq, Wqr, (DOUT * DIN) / 4);
    round_tf32<<<2048, 256>>>(Wk, Wkr, ((NKV * HD) * DIN) / 4);
    round_tf32<<<2048, 256>>>(Wv, Wvr, ((NKV * HD) * DIN) / 4);
    round_tf32<<<2048, 256>>>(Wo, Wor, (DOUT * DOUT) / 4);

    // Fused QKV projection (V written tf32-rounded)
    gemm_qkv<<<dim3(48, SEQ / 128), 128, GEMM_SMEM>>>(xr, Wqr, Wkr, Wvr, Qp, Kp, Vp);

    // RoPE: Q raw, K tf32-rounded on write
    {
        int totQ = SEQ * NH * 64;
        rope_kernel<<<(totQ + 255) / 256, 256>>>(Qp, cosT, sinT, NH, 0);
        int totK = SEQ * NKV * 64;
        rope_kernel<<<(totK + 255) / 256, 256>>>(Kp, cosT, sinT, NKV, 1);
    }

    // Tensor-core flash attention
    attn_mma<<<dim3(SEQ / BQ, NH), 256, ATT_SMEM>>>(Qp, Kp, Vp, Cp);

    // Output projection (both operands pre-rounded)
    gemm_nt<<<dim3(DOUT / 128, SEQ / 128), 128, GEMM_SMEM>>>(Cp, Wor, out, DIN, DOUT);
}

// round 11
// speedup vs baseline: 1.4039x; 1.3869x over previous
#include <cuda_runtime.h>
#include <cuda_fp16.h>
#include <cuda_bf16.h>
#include <math.h>
#include <stdint.h>

// Problem constants
#define SEQ    2048
#define DIN    4096
#define DOUT   4096
#define NH     32
#define NKV    8
#define HD     128
#define GROUP  4

// Scratch buffers
__device__ float  g_Q[SEQ * DOUT];
__device__ float  g_K[SEQ * (NKV * HD)];
__device__ float  g_V[SEQ * (NKV * HD)];
__device__ __half g_ctxh[SEQ * DOUT];
// fp16 operand copies
__device__ __half g_xh[SEQ * DIN];
__device__ __half g_Wqh[DOUT * DIN];
__device__ __half g_Wkh[(NKV * HD) * DIN];
__device__ __half g_Wvh[(NKV * HD) * DIN];
__device__ __half g_Woh[DOUT * DOUT];

__device__ __forceinline__ float f2tf32(float x) {
    float r;
    asm("cvt.rna.tf32.f32 %0, %1;" : "=f"(r) : "f"(x));
    return r;
}

// tf32 mma (attention, unchanged)
__device__ __forceinline__ void mma_tf32(float* c, const uint32_t* a, const uint32_t* b) {
    asm volatile(
        "mma.sync.aligned.m16n8k8.row.col.f32.tf32.tf32.f32 "
        "{%0,%1,%2,%3}, {%4,%5,%6,%7}, {%8,%9}, {%0,%1,%2,%3};"
        : "+f"(c[0]), "+f"(c[1]), "+f"(c[2]), "+f"(c[3])
        : "r"(a[0]), "r"(a[1]), "r"(a[2]), "r"(a[3]), "r"(b[0]), "r"(b[1]));
}

// fp16 mma (GEMMs)
__device__ __forceinline__ void mma_f16(float* c, const uint32_t* a, const uint32_t* b) {
    asm volatile(
        "mma.sync.aligned.m16n8k16.row.col.f32.f16.f16.f32 "
        "{%0,%1,%2,%3}, {%4,%5,%6,%7}, {%8,%9}, {%0,%1,%2,%3};"
        : "+f"(c[0]), "+f"(c[1]), "+f"(c[2]), "+f"(c[3])
        : "r"(a[0]), "r"(a[1]), "r"(a[2]), "r"(a[3]), "r"(b[0]), "r"(b[1]));
}

__device__ __forceinline__ uint32_t smem_u32(const void* p) {
    uint32_t a;
    asm("{ .reg .u64 t; cvta.to.shared.u64 t, %1; cvt.u32.u64 %0, t; }"
        : "=r"(a) : "l"(p));
    return a;
}

__device__ __forceinline__ void cp16(uint32_t dst, const void* src) {
    asm volatile("cp.async.cg.shared.global [%0], [%1], 16;"
                 :: "r"(dst), "l"(src) : "memory");
}
#define CP_COMMIT() asm volatile("cp.async.commit_group;" ::: "memory")
#define CP_WAIT(n)  asm volatile("cp.async.wait_group %0;" :: "n"(n) : "memory")

// ---------------------------------------------------------------------------
// fp32 -> fp16 conversion (grid-stride, float4 in, 8B out)
// ---------------------------------------------------------------------------
__global__ __launch_bounds__(256) void round_f16(
    const float* __restrict__ in, __half* __restrict__ out, int n4)
{
    for (int i = blockIdx.x * blockDim.x + threadIdx.x; i < n4;
         i += gridDim.x * blockDim.x) {
        float4 v = *(const float4*)(in + (size_t)i * 4);
        __half2 h0 = __floats2half2_rn(v.x, v.y);
        __half2 h1 = __floats2half2_rn(v.z, v.w);
        *(uint2*)(out + (size_t)i * 4) =
            make_uint2(*(uint32_t*)&h0, *(uint32_t*)&h1);
    }
}

// ===========================================================================
// fp16 GEMM core: C[128,128] fp32 tile of A[M,K] @ B[N,K]^T, A/B fp16.
// BK=64 halves (row = 128B, same fill/swizzle as validated fp32 version).
// 128 threads, 4 warps, warp tile 64x64, m16n8k16, 3-stage cp.async ring.
// ===========================================================================
#define GS 3
#define STAGE_BYTES 32768    // A 16KB + B 16KB
#define GEMM_SMEM (GS * STAGE_BYTES)

__device__ __forceinline__ void gemm_core_h(
    const __half* __restrict__ A, const __half* __restrict__ B,
    float* __restrict__ C, int K, int ldc, int bm, bool round_out_tf32)
{
    extern __shared__ char sbuf[];
    const uint32_t sbase = smem_u32(sbuf);
    const int tid  = threadIdx.x;
    const int lane = tid & 31;
    const int warp = tid >> 5;
    const int gID  = lane >> 2;
    const int tig  = lane & 3;
    const int wm   = (warp & 1) * 64;
    const int wn   = (warp >> 1) * 64;

    const int fr = tid >> 3;      // 0..15
    const int fc = tid & 7;       // chunk 0..7 (16B = 8 halves)

    float acc[4][8][4];
#pragma unroll
    for (int mi = 0; mi < 4; mi++)
#pragma unroll
        for (int ni = 0; ni < 8; ni++)
#pragma unroll
            for (int j = 0; j < 4; j++) acc[mi][ni][j] = 0.f;

    const int nK = K >> 6;        // chunks of 64 halves

    auto fill = [&](int st, int kt) {
        const uint32_t dA = sbase + st * STAGE_BYTES;
        const uint32_t dB = dA + 16384;
        const __half* gA = A + (size_t)bm * K + kt * 64;
        const __half* gB = B + (size_t)kt * 64;
#pragma unroll
        for (int i = 0; i < 8; i++) {
            const int r = fr + i * 16;
            const uint32_t sw = (uint32_t)(r * 128 + ((fc ^ (r & 7)) * 16));
            cp16(dA + sw, gA + (size_t)r * K + fc * 8);
            cp16(dB + sw, gB + (size_t)r * K + fc * 8);
        }
    };

#pragma unroll
    for (int s = 0; s < GS - 1; s++) {
        if (s < nK) fill(s, s);
        CP_COMMIT();
    }

    for (int kt = 0; kt < nK; kt++) {
        const int nxt = kt + GS - 1;
        if (nxt < nK) fill(nxt % GS, nxt);
        CP_COMMIT();
        CP_WAIT(2);
        __syncthreads();

        const uint32_t* Sa = (const uint32_t*)(sbuf + (kt % GS) * STAGE_BYTES);
        const uint32_t* Sb = Sa + 4096;   // +16KB

#pragma unroll
        for (int kk = 0; kk < 4; kk++) {      // k16 steps
            const int c0 = 2 * kk;
            const int c1 = 2 * kk + 1;

            uint32_t af[4][4], bf[8][2];
#pragma unroll
            for (int mi = 0; mi < 4; mi++) {
                const int r  = wm + mi * 16 + gID;
                const int rx = r & 7;
                af[mi][0] = Sa[r * 32 + ((c0 ^ rx) << 2) + tig];
                af[mi][1] = Sa[(r + 8) * 32 + ((c0 ^ rx) << 2) + tig];
                af[mi][2] = Sa[r * 32 + ((c1 ^ rx) << 2) + tig];
                af[mi][3] = Sa[(r + 8) * 32 + ((c1 ^ rx) << 2) + tig];
            }
#pragma unroll
            for (int ni = 0; ni < 8; ni++) {
                const int n  = wn + ni * 8 + gID;
                const int nx = n & 7;
                bf[ni][0] = Sb[n * 32 + ((c0 ^ nx) << 2) + tig];
                bf[ni][1] = Sb[n * 32 + ((c1 ^ nx) << 2) + tig];
            }
#pragma unroll
            for (int mi = 0; mi < 4; mi++)
#pragma unroll
                for (int ni = 0; ni < 8; ni++)
                    mma_f16(acc[mi][ni], af[mi], bf[ni]);
        }
        __syncthreads();
    }

#pragma unroll
    for (int mi = 0; mi < 4; mi++) {
        const int r0 = bm + wm + mi * 16 + gID;
#pragma unroll
        for (int ni = 0; ni < 8; ni++) {
            const int c0 = wn + ni * 8 + tig * 2;
            float* c = acc[mi][ni];
            if (round_out_tf32) {
                c[0] = f2tf32(c[0]); c[1] = f2tf32(c[1]);
                c[2] = f2tf32(c[2]); c[3] = f2tf32(c[3]);
            }
            *(float2*)(C + (size_t)r0 * ldc + c0)       = make_float2(c[0], c[1]);
            *(float2*)(C + (size_t)(r0 + 8) * ldc + c0) = make_float2(c[2], c[3]);
        }
    }
}

__global__ __launch_bounds__(128, 2) void gemm_qkv(
    const __half* __restrict__ x,
    const __half* __restrict__ Wq, const __half* __restrict__ Wk,
    const __half* __restrict__ Wv,
    float* __restrict__ Q, float* __restrict__ Ko, float* __restrict__ Vo)
{
    const int bn = blockIdx.x;
    const int bm = blockIdx.y * 128;
    const __half* B;
    float* C;
    int ldc, coff;
    bool ro = false;
    if (bn < 32)      { B = Wq; C = Q;  ldc = DOUT; coff = bn * 128; }
    else if (bn < 40) { B = Wk; C = Ko; ldc = NKV * HD; coff = (bn - 32) * 128; }
    else              { B = Wv; C = Vo; ldc = NKV * HD; coff = (bn - 40) * 128; ro = true; }
    gemm_core_h(x, B + (size_t)coff * DIN, C + coff, DIN, ldc, bm, ro);
}

__global__ __launch_bounds__(128, 2) void gemm_nt(
    const __half* __restrict__ A, const __half* __restrict__ B,
    float* __restrict__ C, int K, int N)
{
    const int coff = blockIdx.x * 128;
    gemm_core_h(A, B + (size_t)coff * K, C + coff, K, N, blockIdx.y * 128, false);
}

// ---------------------------------------------------------------------------
// RoPE (in place); optional tf32 rounding of the result (used for K).
// ---------------------------------------------------------------------------
__global__ __launch_bounds__(256) void rope_kernel(
    float* __restrict__ T, const float* __restrict__ cosT,
    const float* __restrict__ sinT, int H, int round_out)
{
    int idx = blockIdx.x * blockDim.x + threadIdx.x;
    int total = SEQ * H * 64;
    if (idx >= total) return;
    int d = idx & 63;
    int h = (idx >> 6) % H;
    int s = idx / (64 * H);

    float* row = T + (size_t)s * (H * HD) + h * HD;
    float x1 = row[d];
    float x2 = row[d + 64];
    float c1 = cosT[s * HD + d],      s1 = sinT[s * HD + d];
    float c2 = cosT[s * HD + d + 64], s2 = sinT[s * HD + d + 64];
    float o1 = fmaf(x1, c1, -x2 * s1);
    float o2 = fmaf(x2, c2,  x1 * s2);
    if (round_out) { o1 = f2tf32(o1); o2 = f2tf32(o2); }
    row[d]      = o1;
    row[d + 64] = o2;
}

// ---------------------------------------------------------------------------
// Tensor-core flash attention (Round 9/10 design, unchanged except the
// epilogue stores ctx as fp16 for the fp16 O-projection).
// ---------------------------------------------------------------------------
#define BQ   128
#define BKV  64
#define PS_  68
#define ATT_STAGE 65536
#define ATT_SMEM  (2 * ATT_STAGE + BQ * PS_ * 4)

__global__ __launch_bounds__(256, 1) void attn_mma(
    const float* __restrict__ Q, const float* __restrict__ K,
    const float* __restrict__ V, __half* __restrict__ ctx)
{
    const int qb  = gridDim.x - 1 - blockIdx.x;
    const int h   = blockIdx.y;
    const int hk  = h >> 2;
    const int tid = threadIdx.x;
    const int lane = tid & 31;
    const int warp = tid >> 5;
    const int gID  = lane >> 2;
    const int tig  = lane & 3;
    const int wrow = warp * 16;

    extern __shared__ char smc[];
    const uint32_t sbase = smem_u32(smc);
    float* Ps = (float*)(smc + 2 * ATT_STAGE);

    const float scale = 0.08838834764831845f;

    auto fill = [&](int buf, int kb) {
        const int r  = tid >> 2;
        const int bc = (tid & 3) * 8;
        const uint32_t kdst = sbase + buf * ATT_STAGE + r * 512;
        const uint32_t vdst = kdst + 32768;
        const float* ksrc = K + (size_t)(kb * BKV + r) * (NKV * HD) + hk * HD;
        const float* vsrc = V + (size_t)(kb * BKV + r) * (NKV * HD) + hk * HD;
#pragma unroll
        for (int j = 0; j < 8; j++) {
            const int ch = bc + j;
            const uint32_t sw = (uint32_t)((ch ^ (r & 7)) << 4);
            cp16(kdst + sw, ksrc + ch * 4);
            cp16(vdst + sw, vsrc + ch * 4);
        }
    };

    uint32_t qf[16][4];
    {
        const float* q0 = Q + (size_t)(qb * BQ + wrow + gID) * DOUT + h * HD;
        const float* q1 = q0 + (size_t)8 * DOUT;
#pragma unroll
        for (int ks = 0; ks < 16; ks++) {
            const int k = ks * 8;
            qf[ks][0] = __float_as_uint(f2tf32(q0[k + tig] * scale));
            qf[ks][1] = __float_as_uint(f2tf32(q1[k + tig] * scale));
            qf[ks][2] = __float_as_uint(f2tf32(q0[k + tig + 4] * scale));
            qf[ks][3] = __float_as_uint(f2tf32(q1[k + tig + 4] * scale));
        }
    }

    float mrow[2] = {-1e30f, -1e30f};
    float lrow[2] = {0.f, 0.f};
    float accO[16][4];
#pragma unroll
    for (int i = 0; i < 16; i++)
#pragma unroll
        for (int j = 0; j < 4; j++) accO[i][j] = 0.f;

    const int nkb = 2 * qb + 2;

    fill(0, 0);
    CP_COMMIT();

    for (int kb = 0; kb < nkb; kb++) {
        const int buf = kb & 1;
        if (kb + 1 < nkb) fill((kb + 1) & 1, kb + 1);
        CP_COMMIT();
        CP_WAIT(1);
        __syncthreads();

        const uint32_t* Ku = (const uint32_t*)(smc + buf * ATT_STAGE);
        const uint32_t* Vu = Ku + 8192;

        float accS[8][4];
#pragma unroll
        for (int i = 0; i < 8; i++)
#pragma unroll
            for (int j = 0; j < 4; j++) accS[i][j] = 0.f;

#pragma unroll
        for (int ks = 0; ks < 16; ks++) {
            const int k4 = ks * 2;
#pragma unroll
            for (int nt = 0; nt < 8; nt++) {
                const int row = nt * 8 + gID;
                const int rx  = row & 7;
                uint32_t b[2];
                b[0] = Ku[row * 128 + ((k4 ^ rx) << 2) + tig];
                b[1] = Ku[row * 128 + (((k4 + 1) ^ rx) << 2) + tig];
                mma_tf32(accS[nt], qf[ks], b);
            }
        }

        if (kb >= 2 * qb) {
            const int q0 = qb * BQ + wrow + gID;
            const int q1 = q0 + 8;
#pragma unroll
            for (int nt = 0; nt < 8; nt++) {
                const int kg = kb * BKV + nt * 8 + 2 * tig;
                if (kg > q0)     accS[nt][0] = -1e30f;
                if (kg + 1 > q0) accS[nt][1] = -1e30f;
                if (kg > q1)     accS[nt][2] = -1e30f;
                if (kg + 1 > q1) accS[nt][3] = -1e30f;
            }
        }

        float mx0 = -1e30f, mx1 = -1e30f;
#pragma unroll
        for (int nt = 0; nt < 8; nt++) {
            mx0 = fmaxf(mx0, fmaxf(accS[nt][0], accS[nt][1]));
            mx1 = fmaxf(mx1, fmaxf(accS[nt][2], accS[nt][3]));
        }
        mx0 = fmaxf(mx0, __shfl_xor_sync(0xffffffffu, mx0, 1));
        mx0 = fmaxf(mx0, __shfl_xor_sync(0xffffffffu, mx0, 2));
        mx1 = fmaxf(mx1, __shfl_xor_sync(0xffffffffu, mx1, 1));
        mx1 = fmaxf(mx1, __shfl_xor_sync(0xffffffffu, mx1, 2));

        float mn0 = fmaxf(mrow[0], mx0);
        float mn1 = fmaxf(mrow[1], mx1);
        float al0 = __expf(mrow[0] - mn0);
        float al1 = __expf(mrow[1] - mn1);
        mrow[0] = mn0; mrow[1] = mn1;

        float ls0 = 0.f, ls1 = 0.f;
        const int pr0 = wrow + gID;
#pragma unroll
        for (int nt = 0; nt < 8; nt++) {
            float p0 = __expf(accS[nt][0] - mn0);
            float p1 = __expf(accS[nt][1] - mn0);
            float p2 = __expf(accS[nt][2] - mn1);
            float p3 = __expf(accS[nt][3] - mn1);
            ls0 += p0 + p1;
            ls1 += p2 + p3;
            const int c = nt * 8 + 2 * tig;
            *(float2*)(Ps + pr0 * PS_ + c)       = make_float2(f2tf32(p0), f2tf32(p1));
            *(float2*)(Ps + (pr0 + 8) * PS_ + c) = make_float2(f2tf32(p2), f2tf32(p3));
        }
        ls0 += __shfl_xor_sync(0xffffffffu, ls0, 1);
        ls0 += __shfl_xor_sync(0xffffffffu, ls0, 2);
        ls1 += __shfl_xor_sync(0xffffffffu, ls1, 1);
        ls1 += __shfl_xor_sync(0xffffffffu, ls1, 2);
        lrow[0] = lrow[0] * al0 + ls0;
        lrow[1] = lrow[1] * al1 + ls1;

#pragma unroll
        for (int nt = 0; nt < 16; nt++) {
            accO[nt][0] *= al0; accO[nt][1] *= al0;
            accO[nt][2] *= al1; accO[nt][3] *= al1;
        }
        __syncwarp();

        const uint32_t* Pu = (const uint32_t*)Ps;
#pragma unroll
        for (int kt = 0; kt < 8; kt++) {
            const int k = kt * 8;
            uint32_t a[4];
            a[0] = Pu[pr0 * PS_ + k + tig];
            a[1] = Pu[(pr0 + 8) * PS_ + k + tig];
            a[2] = Pu[pr0 * PS_ + k + tig + 4];
            a[3] = Pu[(pr0 + 8) * PS_ + k + tig + 4];
            const int row0 = k + tig;
            const int row1 = k + tig + 4;
#pragma unroll
            for (int nt = 0; nt < 16; nt++) {
                const int ch = 2 * nt + (gID >> 2);
                uint32_t b[2];
                b[0] = Vu[row0 * 128 + ((ch ^ tig) << 2) + (gID & 3)];
                b[1] = Vu[row1 * 128 + ((ch ^ (tig + 4)) << 2) + (gID & 3)];
                mma_tf32(accO[nt], a, b);
            }
        }
        __syncthreads();
    }

    // epilogue: normalize, store as fp16 (feeds fp16 O-projection)
    const float li0 = 1.f / lrow[0];
    const float li1 = 1.f / lrow[1];
    const int r0 = qb * BQ + wrow + gID;
    const int r1 = r0 + 8;
#pragma unroll
    for (int nt = 0; nt < 16; nt++) {
        const int c = h * HD + nt * 8 + 2 * tig;
        __half2 h0 = __floats2half2_rn(accO[nt][0] * li0, accO[nt][1] * li0);
        __half2 h1 = __floats2half2_rn(accO[nt][2] * li1, accO[nt][3] * li1);
        *(__half2*)(ctx + (size_t)r0 * DOUT + c) = h0;
        *(__half2*)(ctx + (size_t)r1 * DOUT + c) = h1;
    }
}

// ---------------------------------------------------------------------------
// Launch
// ---------------------------------------------------------------------------
extern "C" void kernel_launch(void* const* d_in, const int* in_sizes, int n_in,
                              void* d_out, int out_size)
{
    const float* x    = (const float*)d_in[0];
    const float* cosT = (const float*)d_in[1];
    const float* sinT = (const float*)d_in[2];
    const float* Wq   = (const float*)d_in[3];
    const float* Wk   = (const float*)d_in[4];
    const float* Wv   = (const float*)d_in[5];
    const float* Wo   = (const float*)d_in[6];
    float* out = (float*)d_out;

    float *Qp, *Kp, *Vp;
    __half *Cph, *xh, *Wqh, *Wkh, *Wvh, *Woh;
    cudaGetSymbolAddress((void**)&Qp, g_Q);
    cudaGetSymbolAddress((void**)&Kp, g_K);
    cudaGetSymbolAddress((void**)&Vp, g_V);
    cudaGetSymbolAddress((void**)&Cph, g_ctxh);
    cudaGetSymbolAddress((void**)&xh, g_xh);
    cudaGetSymbolAddress((void**)&Wqh, g_Wqh);
    cudaGetSymbolAddress((void**)&Wkh, g_Wkh);
    cudaGetSymbolAddress((void**)&Wvh, g_Wvh);
    cudaGetSymbolAddress((void**)&Woh, g_Woh);

    cudaFuncSetAttribute(gemm_qkv, cudaFuncAttributeMaxDynamicSharedMemorySize, GEMM_SMEM);
    cudaFuncSetAttribute(gemm_nt,  cudaFuncAttributeMaxDynamicSharedMemorySize, GEMM_SMEM);
    cudaFuncSetAttribute(attn_mma, cudaFuncAttributeMaxDynamicSharedMemorySize, ATT_SMEM);

    // Convert GEMM operands to fp16
    round_f16<<<2048, 256>>>(x,  xh,  (SEQ * DIN) / 4);
    round_f16<<<2048, 256>>>(Wq, Wqh, (DOUT * DIN) / 4);
    round_f16<<<2048, 256>>>(Wk, Wkh, ((NKV * HD) * DIN) / 4);
    round_f16<<<2048, 256>>>(Wv, Wvh, ((NKV * HD) * DIN) / 4);
    round_f16<<<2048, 256>>>(Wo, Woh, (DOUT * DOUT) / 4);

    // Fused QKV projection (fp16 operands, fp32 out; V tf32-rounded)
    gemm_qkv<<<dim3(48, SEQ / 128), 128, GEMM_SMEM>>>(xh, Wqh, Wkh, Wvh, Qp, Kp, Vp);

    // RoPE: Q raw, K tf32-rounded on write
    {
        int totQ = SEQ * NH * 64;
        rope_kernel<<<(totQ + 255) / 256, 256>>>(Qp, cosT, sinT, NH, 0);
        int totK = SEQ * NKV * 64;
        rope_kernel<<<(totK + 255) / 256, 256>>>(Kp, cosT, sinT, NKV, 1);
    }

    // Tensor-core flash attention (tf32, unchanged)
    attn_mma<<<dim3(SEQ / BQ, NH), 256, ATT_SMEM>>>(Qp, Kp, Vp, Cph);

    // Output projection (fp16 operands)
    gemm_nt<<<dim3(DOUT / 128, SEQ / 128), 128, GEMM_SMEM>>>(Cph, Woh, out, DIN, DOUT);
}

// round 12
// speedup vs baseline: 2.0864x; 1.4861x over previous
#include <cuda_runtime.h>
#include <cuda_fp16.h>
#include <math.h>
#include <stdint.h>

// Problem constants
#define SEQ    2048
#define DIN    4096
#define DOUT   4096
#define NH     32
#define NKV    8
#define HD     128
#define GROUP  4

// Scratch buffers
__device__ float  g_Q[SEQ * DOUT];
__device__ float  g_K[SEQ * (NKV * HD)];
__device__ float  g_V[SEQ * (NKV * HD)];
__device__ __half g_Kh[SEQ * (NKV * HD)];          // fp16 K (post-RoPE)
__device__ __half g_Vth[(NKV * HD) * SEQ];         // fp16 V transposed [d][s]
__device__ __half g_ctxh[SEQ * DOUT];
// fp16 operand copies
__device__ __half g_xh[SEQ * DIN];
__device__ __half g_Wqh[DOUT * DIN];
__device__ __half g_Wkh[(NKV * HD) * DIN];
__device__ __half g_Wvh[(NKV * HD) * DIN];
__device__ __half g_Woh[DOUT * DOUT];

// fp16 mma
__device__ __forceinline__ void mma_f16(float* c, const uint32_t* a, const uint32_t* b) {
    asm volatile(
        "mma.sync.aligned.m16n8k16.row.col.f32.f16.f16.f32 "
        "{%0,%1,%2,%3}, {%4,%5,%6,%7}, {%8,%9}, {%0,%1,%2,%3};"
        : "+f"(c[0]), "+f"(c[1]), "+f"(c[2]), "+f"(c[3])
        : "r"(a[0]), "r"(a[1]), "r"(a[2]), "r"(a[3]), "r"(b[0]), "r"(b[1]));
}

__device__ __forceinline__ uint32_t smem_u32(const void* p) {
    uint32_t a;
    asm("{ .reg .u64 t; cvta.to.shared.u64 t, %1; cvt.u32.u64 %0, t; }"
        : "=r"(a) : "l"(p));
    return a;
}

__device__ __forceinline__ void cp16(uint32_t dst, const void* src) {
    asm volatile("cp.async.cg.shared.global [%0], [%1], 16;"
                 :: "r"(dst), "l"(src) : "memory");
}
#define CP_COMMIT() asm volatile("cp.async.commit_group;" ::: "memory")
#define CP_WAIT(n)  asm volatile("cp.async.wait_group %0;" :: "n"(n) : "memory")

__device__ __forceinline__ uint32_t pack_h2(float a, float b) {
    __half2 h = __floats2half2_rn(a, b);
    return *(uint32_t*)&h;
}

// ---------------------------------------------------------------------------
// fp32 -> fp16 conversion (grid-stride)
// ---------------------------------------------------------------------------
__global__ __launch_bounds__(256) void round_f16(
    const float* __restrict__ in, __half* __restrict__ out, int n4)
{
    for (int i = blockIdx.x * blockDim.x + threadIdx.x; i < n4;
         i += gridDim.x * blockDim.x) {
        float4 v = *(const float4*)(in + (size_t)i * 4);
        __half2 h0 = __floats2half2_rn(v.x, v.y);
        __half2 h1 = __floats2half2_rn(v.z, v.w);
        *(uint2*)(out + (size_t)i * 4) =
            make_uint2(*(uint32_t*)&h0, *(uint32_t*)&h1);
    }
}

// ---------------------------------------------------------------------------
// V transpose: [SEQ][1024] fp32 -> [1024][SEQ] fp16 (32x32 tiles)
// ---------------------------------------------------------------------------
__global__ __launch_bounds__(256) void vtrans(
    const float* __restrict__ V, __half* __restrict__ Vt)
{
    __shared__ float t[32][33];
    const int s0 = blockIdx.x * 32;
    const int c0 = blockIdx.y * 32;
    const int tx = threadIdx.x & 31;
    const int ty = threadIdx.x >> 5;    // 0..7
#pragma unroll
    for (int i = ty; i < 32; i += 8)
        t[i][tx] = V[(size_t)(s0 + i) * (NKV * HD) + c0 + tx];
    __syncthreads();
#pragma unroll
    for (int i = ty; i < 32; i += 8)
        Vt[(size_t)(c0 + i) * SEQ + s0 + tx] = __float2half_rn(t[tx][i]);
}

// ===========================================================================
// fp16 GEMM core (Round 11 — validated)
// ===========================================================================
#define GS 3
#define STAGE_BYTES 32768
#define GEMM_SMEM (GS * STAGE_BYTES)

__device__ __forceinline__ void gemm_core_h(
    const __half* __restrict__ A, const __half* __restrict__ B,
    float* __restrict__ C, int K, int ldc, int bm)
{
    extern __shared__ char sbuf[];
    const uint32_t sbase = smem_u32(sbuf);
    const int tid  = threadIdx.x;
    const int lane = tid & 31;
    const int warp = tid >> 5;
    const int gID  = lane >> 2;
    const int tig  = lane & 3;
    const int wm   = (warp & 1) * 64;
    const int wn   = (warp >> 1) * 64;

    const int fr = tid >> 3;
    const int fc = tid & 7;

    float acc[4][8][4];
#pragma unroll
    for (int mi = 0; mi < 4; mi++)
#pragma unroll
        for (int ni = 0; ni < 8; ni++)
#pragma unroll
            for (int j = 0; j < 4; j++) acc[mi][ni][j] = 0.f;

    const int nK = K >> 6;

    auto fill = [&](int st, int kt) {
        const uint32_t dA = sbase + st * STAGE_BYTES;
        const uint32_t dB = dA + 16384;
        const __half* gA = A + (size_t)bm * K + kt * 64;
        const __half* gB = B + (size_t)kt * 64;
#pragma unroll
        for (int i = 0; i < 8; i++) {
            const int r = fr + i * 16;
            const uint32_t sw = (uint32_t)(r * 128 + ((fc ^ (r & 7)) * 16));
            cp16(dA + sw, gA + (size_t)r * K + fc * 8);
            cp16(dB + sw, gB + (size_t)r * K + fc * 8);
        }
    };

#pragma unroll
    for (int s = 0; s < GS - 1; s++) {
        if (s < nK) fill(s, s);
        CP_COMMIT();
    }

    for (int kt = 0; kt < nK; kt++) {
        const int nxt = kt + GS - 1;
        if (nxt < nK) fill(nxt % GS, nxt);
        CP_COMMIT();
        CP_WAIT(2);
        __syncthreads();

        const uint32_t* Sa = (const uint32_t*)(sbuf + (kt % GS) * STAGE_BYTES);
        const uint32_t* Sb = Sa + 4096;

#pragma unroll
        for (int kk = 0; kk < 4; kk++) {
            const int c0 = 2 * kk;
            const int c1 = 2 * kk + 1;

            uint32_t af[4][4], bf[8][2];
#pragma unroll
            for (int mi = 0; mi < 4; mi++) {
                const int r  = wm + mi * 16 + gID;
                const int rx = r & 7;
                af[mi][0] = Sa[r * 32 + ((c0 ^ rx) << 2) + tig];
                af[mi][1] = Sa[(r + 8) * 32 + ((c0 ^ rx) << 2) + tig];
                af[mi][2] = Sa[r * 32 + ((c1 ^ rx) << 2) + tig];
                af[mi][3] = Sa[(r + 8) * 32 + ((c1 ^ rx) << 2) + tig];
            }
#pragma unroll
            for (int ni = 0; ni < 8; ni++) {
                const int n  = wn + ni * 8 + gID;
                const int nx = n & 7;
                bf[ni][0] = Sb[n * 32 + ((c0 ^ nx) << 2) + tig];
                bf[ni][1] = Sb[n * 32 + ((c1 ^ nx) << 2) + tig];
            }
#pragma unroll
            for (int mi = 0; mi < 4; mi++)
#pragma unroll
                for (int ni = 0; ni < 8; ni++)
                    mma_f16(acc[mi][ni], af[mi], bf[ni]);
        }
        __syncthreads();
    }

#pragma unroll
    for (int mi = 0; mi < 4; mi++) {
        const int r0 = bm + wm + mi * 16 + gID;
#pragma unroll
        for (int ni = 0; ni < 8; ni++) {
            const int c0 = wn + ni * 8 + tig * 2;
            const float* c = acc[mi][ni];
            *(float2*)(C + (size_t)r0 * ldc + c0)       = make_float2(c[0], c[1]);
            *(float2*)(C + (size_t)(r0 + 8) * ldc + c0) = make_float2(c[2], c[3]);
        }
    }
}

__global__ __launch_bounds__(128, 2) void gemm_qkv(
    const __half* __restrict__ x,
    const __half* __restrict__ Wq, const __half* __restrict__ Wk,
    const __half* __restrict__ Wv,
    float* __restrict__ Q, float* __restrict__ Ko, float* __restrict__ Vo)
{
    const int bn = blockIdx.x;
    const int bm = blockIdx.y * 128;
    const __half* B;
    float* C;
    int ldc, coff;
    if (bn < 32)      { B = Wq; C = Q;  ldc = DOUT; coff = bn * 128; }
    else if (bn < 40) { B = Wk; C = Ko; ldc = NKV * HD; coff = (bn - 32) * 128; }
    else              { B = Wv; C = Vo; ldc = NKV * HD; coff = (bn - 40) * 128; }
    gemm_core_h(x, B + (size_t)coff * DIN, C + coff, DIN, ldc, bm);
}

__global__ __launch_bounds__(128, 2) void gemm_nt(
    const __half* __restrict__ A, const __half* __restrict__ B,
    float* __restrict__ C, int K, int N)
{
    const int coff = blockIdx.x * 128;
    gemm_core_h(A, B + (size_t)coff * K, C + coff, K, N, blockIdx.y * 128);
}

// ---------------------------------------------------------------------------
// RoPE for Q (fp32 in-place)
// ---------------------------------------------------------------------------
__global__ __launch_bounds__(256) void rope_q(
    float* __restrict__ T, const float* __restrict__ cosT,
    const float* __restrict__ sinT)
{
    int idx = blockIdx.x * blockDim.x + threadIdx.x;
    int total = SEQ * NH * 64;
    if (idx >= total) return;
    int d = idx & 63;
    int h = (idx >> 6) % NH;
    int s = idx / (64 * NH);

    float* row = T + (size_t)s * DOUT + h * HD;
    float x1 = row[d];
    float x2 = row[d + 64];
    row[d]      = fmaf(x1, cosT[s * HD + d],      -x2 * sinT[s * HD + d]);
    row[d + 64] = fmaf(x2, cosT[s * HD + d + 64],  x1 * sinT[s * HD + d + 64]);
}

// RoPE for K: fp32 in, fp16 out (separate buffer)
__global__ __launch_bounds__(256) void rope_k_h(
    const float* __restrict__ T, __half* __restrict__ Th,
    const float* __restrict__ cosT, const float* __restrict__ sinT)
{
    int idx = blockIdx.x * blockDim.x + threadIdx.x;
    int total = SEQ * NKV * 64;
    if (idx >= total) return;
    int d = idx & 63;
    int h = (idx >> 6) % NKV;
    int s = idx / (64 * NKV);

    const float* row = T + (size_t)s * (NKV * HD) + h * HD;
    __half* rowh = Th + (size_t)s * (NKV * HD) + h * HD;
    float x1 = row[d];
    float x2 = row[d + 64];
    rowh[d]      = __float2half_rn(fmaf(x1, cosT[s * HD + d],      -x2 * sinT[s * HD + d]));
    rowh[d + 64] = __float2half_rn(fmaf(x2, cosT[s * HD + d + 64],  x1 * sinT[s * HD + d + 64]));
}

// ---------------------------------------------------------------------------
// fp16 tensor-core flash attention. m16n8k16; K fp16 [s][d]; V fp16 transposed
// [d][s]; P staged fp16; fp32 softmax/accumulators.
// K tile: 64 rows x 256B (16 chunks, XOR swizzle). V tile: 128 rows x 128B
// (8 chunks). Double-buffered cp.async; Q in registers.
// ---------------------------------------------------------------------------
#define BQ   128
#define BKV  64
#define PSH  72      // Ps row stride in halves (36 uint32)
#define ATT_STAGE 32768
#define ATT_SMEM  (2 * ATT_STAGE + BQ * PSH * 2)

__global__ __launch_bounds__(256, 1) void attn_mma(
    const float* __restrict__ Q, const __half* __restrict__ Kh,
    const __half* __restrict__ Vt, __half* __restrict__ ctx)
{
    const int qb  = gridDim.x - 1 - blockIdx.x;
    const int h   = blockIdx.y;
    const int hk  = h >> 2;
    const int tid = threadIdx.x;
    const int lane = tid & 31;
    const int warp = tid >> 5;
    const int gID  = lane >> 2;
    const int tig  = lane & 3;
    const int wrow = warp * 16;

    extern __shared__ char smc[];
    const uint32_t sbase = smem_u32(smc);
    __half* Psh = (__half*)(smc + 2 * ATT_STAGE);

    const float scale = 0.08838834764831845f;

    auto fill = [&](int buf, int kb) {
        // K: 64 rows x 16 chunks
        {
            const int r  = tid >> 2;
            const uint32_t kdst = sbase + buf * ATT_STAGE + r * 256;
            const __half* ksrc = Kh + (size_t)(kb * BKV + r) * (NKV * HD) + hk * HD;
#pragma unroll
            for (int j = 0; j < 4; j++) {
                const int ch = (tid & 3) * 4 + j;
                cp16(kdst + (uint32_t)((ch ^ (r & 7)) << 4), ksrc + ch * 8);
            }
        }
        // V (transposed): 128 rows x 8 chunks
        {
            const int r  = tid >> 1;
            const uint32_t vdst = sbase + buf * ATT_STAGE + 16384 + r * 128;
            const __half* vsrc = Vt + (size_t)(hk * HD + r) * SEQ + kb * BKV;
#pragma unroll
            for (int j = 0; j < 4; j++) {
                const int ch = (tid & 1) * 4 + j;
                cp16(vdst + (uint32_t)((ch ^ (r & 7)) << 4), vsrc + ch * 8);
            }
        }
    };

    // ---- Q A-fragments (fp16, scaled) ----
    uint32_t qf[8][4];
    {
        const float* q0 = Q + (size_t)(qb * BQ + wrow + gID) * DOUT + h * HD;
        const float* q1 = q0 + (size_t)8 * DOUT;
#pragma unroll
        for (int kk = 0; kk < 8; kk++) {
            const int k = kk * 16;
            qf[kk][0] = pack_h2(q0[k + 2 * tig] * scale, q0[k + 2 * tig + 1] * scale);
            qf[kk][1] = pack_h2(q1[k + 2 * tig] * scale, q1[k + 2 * tig + 1] * scale);
            qf[kk][2] = pack_h2(q0[k + 8 + 2 * tig] * scale, q0[k + 9 + 2 * tig] * scale);
            qf[kk][3] = pack_h2(q1[k + 8 + 2 * tig] * scale, q1[k + 9 + 2 * tig] * scale);
        }
    }

    float mrow[2] = {-1e30f, -1e30f};
    float lrow[2] = {0.f, 0.f};
    float accO[16][4];
#pragma unroll
    for (int i = 0; i < 16; i++)
#pragma unroll
        for (int j = 0; j < 4; j++) accO[i][j] = 0.f;

    const int nkb = 2 * qb + 2;

    fill(0, 0);
    CP_COMMIT();

    for (int kb = 0; kb < nkb; kb++) {
        const int buf = kb & 1;
        if (kb + 1 < nkb) fill((kb + 1) & 1, kb + 1);
        CP_COMMIT();
        CP_WAIT(1);
        __syncthreads();

        const uint32_t* Ku = (const uint32_t*)(smc + buf * ATT_STAGE);
        const uint32_t* Vu = (const uint32_t*)(smc + buf * ATT_STAGE + 16384);

        // ---- S = Q @ K^T : warp computes 16x64 ----
        float accS[8][4];
#pragma unroll
        for (int i = 0; i < 8; i++)
#pragma unroll
            for (int j = 0; j < 4; j++) accS[i][j] = 0.f;

#pragma unroll
        for (int kk = 0; kk < 8; kk++) {
            const int c0 = 2 * kk;
            const int c1 = 2 * kk + 1;
#pragma unroll
            for (int nt = 0; nt < 8; nt++) {
                const int n = nt * 8 + gID;     // n & 7 == gID
                uint32_t b[2];
                b[0] = Ku[n * 64 + ((c0 ^ gID) << 2) + tig];
                b[1] = Ku[n * 64 + ((c1 ^ gID) << 2) + tig];
                mma_f16(accS[nt], qf[kk], b);
            }
        }

        // ---- causal mask ----
        if (kb >= 2 * qb) {
            const int q0 = qb * BQ + wrow + gID;
            const int q1 = q0 + 8;
#pragma unroll
            for (int nt = 0; nt < 8; nt++) {
                const int kg = kb * BKV + nt * 8 + 2 * tig;
                if (kg > q0)     accS[nt][0] = -1e30f;
                if (kg + 1 > q0) accS[nt][1] = -1e30f;
                if (kg > q1)     accS[nt][2] = -1e30f;
                if (kg + 1 > q1) accS[nt][3] = -1e30f;
            }
        }

        // ---- online softmax (fp32) ----
        float mx0 = -1e30f, mx1 = -1e30f;
#pragma unroll
        for (int nt = 0; nt < 8; nt++) {
            mx0 = fmaxf(mx0, fmaxf(accS[nt][0], accS[nt][1]));
            mx1 = fmaxf(mx1, fmaxf(accS[nt][2], accS[nt][3]));
        }
        mx0 = fmaxf(mx0, __shfl_xor_sync(0xffffffffu, mx0, 1));
        mx0 = fmaxf(mx0, __shfl_xor_sync(0xffffffffu, mx0, 2));
        mx1 = fmaxf(mx1, __shfl_xor_sync(0xffffffffu, mx1, 1));
        mx1 = fmaxf(mx1, __shfl_xor_sync(0xffffffffu, mx1, 2));

        float mn0 = fmaxf(mrow[0], mx0);
        float mn1 = fmaxf(mrow[1], mx1);
        float al0 = __expf(mrow[0] - mn0);
        float al1 = __expf(mrow[1] - mn1);
        mrow[0] = mn0; mrow[1] = mn1;

        float ls0 = 0.f, ls1 = 0.f;
        const int pr0 = wrow + gID;
#pragma unroll
        for (int nt = 0; nt < 8; nt++) {
            float p0 = __expf(accS[nt][0] - mn0);
            float p1 = __expf(accS[nt][1] - mn0);
            float p2 = __expf(accS[nt][2] - mn1);
            float p3 = __expf(accS[nt][3] - mn1);
            ls0 += p0 + p1;
            ls1 += p2 + p3;
            const int c = nt * 8 + 2 * tig;
            __half2 h0 = __floats2half2_rn(p0, p1);
            __half2 h1 = __floats2half2_rn(p2, p3);
            *(__half2*)(Psh + pr0 * PSH + c)       = h0;
            *(__half2*)(Psh + (pr0 + 8) * PSH + c) = h1;
        }
        ls0 += __shfl_xor_sync(0xffffffffu, ls0, 1);
        ls0 += __shfl_xor_sync(0xffffffffu, ls0, 2);
        ls1 += __shfl_xor_sync(0xffffffffu, ls1, 1);
        ls1 += __shfl_xor_sync(0xffffffffu, ls1, 2);
        lrow[0] = lrow[0] * al0 + ls0;
        lrow[1] = lrow[1] * al1 + ls1;

#pragma unroll
        for (int nt = 0; nt < 16; nt++) {
            accO[nt][0] *= al0; accO[nt][1] *= al0;
            accO[nt][2] *= al1; accO[nt][3] *= al1;
        }
        __syncwarp();   // Ps rows are warp-private

        // ---- O += P @ V : warp computes 16x128 ----
        const uint32_t* Pu = (const uint32_t*)Psh;
#pragma unroll
        for (int kk = 0; kk < 4; kk++) {
            const int c0 = 2 * kk;
            const int c1 = 2 * kk + 1;
            uint32_t a[4];
            a[0] = Pu[pr0 * (PSH / 2) + kk * 8 + tig];
            a[1] = Pu[(pr0 + 8) * (PSH / 2) + kk * 8 + tig];
            a[2] = Pu[pr0 * (PSH / 2) + kk * 8 + 4 + tig];
            a[3] = Pu[(pr0 + 8) * (PSH / 2) + kk * 8 + 4 + tig];
#pragma unroll
            for (int nt = 0; nt < 16; nt++) {
                const int n = nt * 8 + gID;     // d-row; n & 7 == gID
                uint32_t b[2];
                b[0] = Vu[n * 32 + ((c0 ^ gID) << 2) + tig];
                b[1] = Vu[n * 32 + ((c1 ^ gID) << 2) + tig];
                mma_f16(accO[nt], a, b);
            }
        }
        __syncthreads();
    }

    // epilogue: normalize, store as fp16 (feeds fp16 O-projection)
    const float li0 = 1.f / lrow[0];
    const float li1 = 1.f / lrow[1];
    const int r0 = qb * BQ + wrow + gID;
    const int r1 = r0 + 8;
#pragma unroll
    for (int nt = 0; nt < 16; nt++) {
        const int c = h * HD + nt * 8 + 2 * tig;
        __half2 h0 = __floats2half2_rn(accO[nt][0] * li0, accO[nt][1] * li0);
        __half2 h1 = __floats2half2_rn(accO[nt][2] * li1, accO[nt][3] * li1);
        *(__half2*)(ctx + (size_t)r0 * DOUT + c) = h0;
        *(__half2*)(ctx + (size_t)r1 * DOUT + c) = h1;
    }
}

// ---------------------------------------------------------------------------
// Launch
// ---------------------------------------------------------------------------
extern "C" void kernel_launch(void* const* d_in, const int* in_sizes, int n_in,
                              void* d_out, int out_size)
{
    const float* x    = (const float*)d_in[0];
    const float* cosT = (const float*)d_in[1];
    const float* sinT = (const float*)d_in[2];
    const float* Wq   = (const float*)d_in[3];
    const float* Wk   = (const float*)d_in[4];
    const float* Wv   = (const float*)d_in[5];
    const float* Wo   = (const float*)d_in[6];
    float* out = (float*)d_out;

    float *Qp, *Kp, *Vp;
    __half *Kph, *Vtp, *Cph, *xh, *Wqh, *Wkh, *Wvh, *Woh;
    cudaGetSymbolAddress((void**)&Qp, g_Q);
    cudaGetSymbolAddress((void**)&Kp, g_K);
    cudaGetSymbolAddress((void**)&Vp, g_V);
    cudaGetSymbolAddress((void**)&Kph, g_Kh);
    cudaGetSymbolAddress((void**)&Vtp, g_Vth);
    cudaGetSymbolAddress((void**)&Cph, g_ctxh);
    cudaGetSymbolAddress((void**)&xh, g_xh);
    cudaGetSymbolAddress((void**)&Wqh, g_Wqh);
    cudaGetSymbolAddress((void**)&Wkh, g_Wkh);
    cudaGetSymbolAddress((void**)&Wvh, g_Wvh);
    cudaGetSymbolAddress((void**)&Woh, g_Woh);

    cudaFuncSetAttribute(gemm_qkv, cudaFuncAttributeMaxDynamicSharedMemorySize, GEMM_SMEM);
    cudaFuncSetAttribute(gemm_nt,  cudaFuncAttributeMaxDynamicSharedMemorySize, GEMM_SMEM);
    cudaFuncSetAttribute(attn_mma, cudaFuncAttributeMaxDynamicSharedMemorySize, ATT_SMEM);

    // Convert GEMM operands to fp16
    round_f16<<<2048, 256>>>(x,  xh,  (SEQ * DIN) / 4);
    round_f16<<<2048, 256>>>(Wq, Wqh, (DOUT * DIN) / 4);
    round_f16<<<2048, 256>>>(Wk, Wkh, ((NKV * HD) * DIN) / 4);
    round_f16<<<2048, 256>>>(Wv, Wvh, ((NKV * HD) * DIN) / 4);
    round_f16<<<2048, 256>>>(Wo, Woh, (DOUT * DOUT) / 4);

    // Fused QKV projection (fp16 in, fp32 out)
    gemm_qkv<<<dim3(48, SEQ / 128), 128, GEMM_SMEM>>>(xh, Wqh, Wkh, Wvh, Qp, Kp, Vp);

    // RoPE: Q fp32 in-place; K -> fp16 buffer
    {
        int totQ = SEQ * NH * 64;
        rope_q<<<(totQ + 255) / 256, 256>>>(Qp, cosT, sinT);
        int totK = SEQ * NKV * 64;
        rope_k_h<<<(totK + 255) / 256, 256>>>(Kp, Kph, cosT, sinT);
    }

    // V transpose -> fp16 [d][s]
    vtrans<<<dim3(SEQ / 32, (NKV * HD) / 32), 256>>>(Vp, Vtp);

    // fp16 tensor-core flash attention
    attn_mma<<<dim3(SEQ / BQ, NH), 256, ATT_SMEM>>>(Qp, Kph, Vtp, Cph);

    // Output projection (fp16 operands)
    gemm_nt<<<dim3(DOUT / 128, SEQ / 128), 128, GEMM_SMEM>>>(Cph, Woh, out, DIN, DOUT);
}

// round 13
// speedup vs baseline: 2.1745x; 1.0422x over previous
#include <cuda_runtime.h>
#include <cuda_fp16.h>
#include <math.h>
#include <stdint.h>

// Problem constants
#define SEQ    2048
#define DIN    4096
#define DOUT   4096
#define NH     32
#define NKV    8
#define HD     128
#define GROUP  4

// Scratch buffers
__device__ float  g_Q[SEQ * DOUT];
__device__ float  g_K[SEQ * (NKV * HD)];
__device__ float  g_V[SEQ * (NKV * HD)];
__device__ __half g_Kh[SEQ * (NKV * HD)];
__device__ __half g_Vth[(NKV * HD) * SEQ];
__device__ __half g_ctxh[SEQ * DOUT];
__device__ __half g_xh[SEQ * DIN];
__device__ __half g_Wqh[DOUT * DIN];
__device__ __half g_Wkh[(NKV * HD) * DIN];
__device__ __half g_Wvh[(NKV * HD) * DIN];
__device__ __half g_Woh[DOUT * DOUT];

// fp16 mma
__device__ __forceinline__ void mma_f16(float* c, const uint32_t* a, const uint32_t* b) {
    asm volatile(
        "mma.sync.aligned.m16n8k16.row.col.f32.f16.f16.f32 "
        "{%0,%1,%2,%3}, {%4,%5,%6,%7}, {%8,%9}, {%0,%1,%2,%3};"
        : "+f"(c[0]), "+f"(c[1]), "+f"(c[2]), "+f"(c[3])
        : "r"(a[0]), "r"(a[1]), "r"(a[2]), "r"(a[3]), "r"(b[0]), "r"(b[1]));
}

__device__ __forceinline__ void ldsm4(uint32_t* r, uint32_t addr) {
    asm volatile("ldmatrix.sync.aligned.m8n8.x4.shared.b16 {%0,%1,%2,%3}, [%4];"
        : "=r"(r[0]), "=r"(r[1]), "=r"(r[2]), "=r"(r[3]) : "r"(addr));
}

__device__ __forceinline__ uint32_t smem_u32(const void* p) {
    uint32_t a;
    asm("{ .reg .u64 t; cvta.to.shared.u64 t, %1; cvt.u32.u64 %0, t; }"
        : "=r"(a) : "l"(p));
    return a;
}

__device__ __forceinline__ void cp16(uint32_t dst, const void* src) {
    asm volatile("cp.async.cg.shared.global [%0], [%1], 16;"
                 :: "r"(dst), "l"(src) : "memory");
}
#define CP_COMMIT() asm volatile("cp.async.commit_group;" ::: "memory")
#define CP_WAIT(n)  asm volatile("cp.async.wait_group %0;" :: "n"(n) : "memory")

__device__ __forceinline__ uint32_t pack_h2(float a, float b) {
    __half2 h = __floats2half2_rn(a, b);
    return *(uint32_t*)&h;
}

// ---------------------------------------------------------------------------
// fp32 -> fp16 conversion (grid-stride)
// ---------------------------------------------------------------------------
__global__ __launch_bounds__(256) void round_f16(
    const float* __restrict__ in, __half* __restrict__ out, int n4)
{
    for (int i = blockIdx.x * blockDim.x + threadIdx.x; i < n4;
         i += gridDim.x * blockDim.x) {
        float4 v = *(const float4*)(in + (size_t)i * 4);
        __half2 h0 = __floats2half2_rn(v.x, v.y);
        __half2 h1 = __floats2half2_rn(v.z, v.w);
        *(uint2*)(out + (size_t)i * 4) =
            make_uint2(*(uint32_t*)&h0, *(uint32_t*)&h1);
    }
}

// ---------------------------------------------------------------------------
// V transpose: [SEQ][1024] fp32 -> [1024][SEQ] fp16
// ---------------------------------------------------------------------------
__global__ __launch_bounds__(256) void vtrans(
    const float* __restrict__ V, __half* __restrict__ Vt)
{
    __shared__ float t[32][33];
    const int s0 = blockIdx.x * 32;
    const int c0 = blockIdx.y * 32;
    const int tx = threadIdx.x & 31;
    const int ty = threadIdx.x >> 5;
#pragma unroll
    for (int i = ty; i < 32; i += 8)
        t[i][tx] = V[(size_t)(s0 + i) * (NKV * HD) + c0 + tx];
    __syncthreads();
#pragma unroll
    for (int i = ty; i < 32; i += 8)
        Vt[(size_t)(c0 + i) * SEQ + s0 + tx] = __float2half_rn(t[tx][i]);
}

// ===========================================================================
// fp16 GEMM core — Round 13: fragment loads via ldmatrix.x4 (bit-identical
// register contents to the Round-12 scalar LDS version).
// ===========================================================================
#define GS 3
#define STAGE_BYTES 32768
#define GEMM_SMEM (GS * STAGE_BYTES)

__device__ __forceinline__ void gemm_core_h(
    const __half* __restrict__ A, const __half* __restrict__ B,
    float* __restrict__ C, int K, int ldc, int bm)
{
    extern __shared__ char sbuf[];
    const uint32_t sbase = smem_u32(sbuf);
    const int tid  = threadIdx.x;
    const int lane = tid & 31;
    const int warp = tid >> 5;
    const int gID  = lane >> 2;
    const int tig  = lane & 3;
    const int wm   = (warp & 1) * 64;
    const int wn   = (warp >> 1) * 64;

    const int fr = tid >> 3;
    const int fc = tid & 7;

    // ldmatrix per-lane row/chunk decomposition
    const int l7    = lane & 7;                     // row-in-8 AND swizzle xor
    const int aRowL = l7 + ((lane >> 3) & 1) * 8;   // A: mat0/1 rows, mat2/3 k-half
    const int aChO  = lane >> 4;
    const int bRowL = l7 + (lane >> 4) * 8;         // B: mat0/1 k-halves, mat2/3 rows+8
    const int bChO  = (lane >> 3) & 1;

    float acc[4][8][4];
#pragma unroll
    for (int mi = 0; mi < 4; mi++)
#pragma unroll
        for (int ni = 0; ni < 8; ni++)
#pragma unroll
            for (int j = 0; j < 4; j++) acc[mi][ni][j] = 0.f;

    const int nK = K >> 6;

    auto fill = [&](int st, int kt) {
        const uint32_t dA = sbase + st * STAGE_BYTES;
        const uint32_t dB = dA + 16384;
        const __half* gA = A + (size_t)bm * K + kt * 64;
        const __half* gB = B + (size_t)kt * 64;
#pragma unroll
        for (int i = 0; i < 8; i++) {
            const int r = fr + i * 16;
            const uint32_t sw = (uint32_t)(r * 128 + ((fc ^ (r & 7)) * 16));
            cp16(dA + sw, gA + (size_t)r * K + fc * 8);
            cp16(dB + sw, gB + (size_t)r * K + fc * 8);
        }
    };

#pragma unroll
    for (int s = 0; s < GS - 1; s++) {
        if (s < nK) fill(s, s);
        CP_COMMIT();
    }

    for (int kt = 0; kt < nK; kt++) {
        const int nxt = kt + GS - 1;
        if (nxt < nK) fill(nxt % GS, nxt);
        CP_COMMIT();
        CP_WAIT(2);
        __syncthreads();

        const uint32_t sa = sbase + (kt % GS) * STAGE_BYTES;
        const uint32_t sb = sa + 16384;
        // per-lane row bases (constant across kk)
        uint32_t aBase[4], bBase[4];
#pragma unroll
        for (int mi = 0; mi < 4; mi++)
            aBase[mi] = sa + (uint32_t)((wm + mi * 16 + aRowL) * 128);
#pragma unroll
        for (int nj = 0; nj < 4; nj++)
            bBase[nj] = sb + (uint32_t)((wn + nj * 16 + bRowL) * 128);

#pragma unroll
        for (int kk = 0; kk < 4; kk++) {
            const int chA = 2 * kk + aChO;
            const int chB = 2 * kk + bChO;
            const uint32_t swA = (uint32_t)((chA ^ l7) << 4);
            const uint32_t swB = (uint32_t)((chB ^ l7) << 4);

            uint32_t af[4][4], bf[8][2];
#pragma unroll
            for (int mi = 0; mi < 4; mi++)
                ldsm4(af[mi], aBase[mi] + swA);
#pragma unroll
            for (int nj = 0; nj < 4; nj++) {
                uint32_t tmp[4];
                ldsm4(tmp, bBase[nj] + swB);
                bf[2 * nj][0]     = tmp[0];
                bf[2 * nj][1]     = tmp[1];
                bf[2 * nj + 1][0] = tmp[2];
                bf[2 * nj + 1][1] = tmp[3];
            }
#pragma unroll
            for (int mi = 0; mi < 4; mi++)
#pragma unroll
                for (int ni = 0; ni < 8; ni++)
                    mma_f16(acc[mi][ni], af[mi], bf[ni]);
        }
        __syncthreads();
    }

#pragma unroll
    for (int mi = 0; mi < 4; mi++) {
        const int r0 = bm + wm + mi * 16 + gID;
#pragma unroll
        for (int ni = 0; ni < 8; ni++) {
            const int c0 = wn + ni * 8 + tig * 2;
            const float* c = acc[mi][ni];
            *(float2*)(C + (size_t)r0 * ldc + c0)       = make_float2(c[0], c[1]);
            *(float2*)(C + (size_t)(r0 + 8) * ldc + c0) = make_float2(c[2], c[3]);
        }
    }
}

__global__ __launch_bounds__(128, 2) void gemm_qkv(
    const __half* __restrict__ x,
    const __half* __restrict__ Wq, const __half* __restrict__ Wk,
    const __half* __restrict__ Wv,
    float* __restrict__ Q, float* __restrict__ Ko, float* __restrict__ Vo)
{
    const int bn = blockIdx.x;
    const int bm = blockIdx.y * 128;
    const __half* B;
    float* C;
    int ldc, coff;
    if (bn < 32)      { B = Wq; C = Q;  ldc = DOUT; coff = bn * 128; }
    else if (bn < 40) { B = Wk; C = Ko; ldc = NKV * HD; coff = (bn - 32) * 128; }
    else              { B = Wv; C = Vo; ldc = NKV * HD; coff = (bn - 40) * 128; }
    gemm_core_h(x, B + (size_t)coff * DIN, C + coff, DIN, ldc, bm);
}

__global__ __launch_bounds__(128, 2) void gemm_nt(
    const __half* __restrict__ A, const __half* __restrict__ B,
    float* __restrict__ C, int K, int N)
{
    const int coff = blockIdx.x * 128;
    gemm_core_h(A, B + (size_t)coff * K, C + coff, K, N, blockIdx.y * 128);
}

// ---------------------------------------------------------------------------
// RoPE for Q (fp32 in-place)
// ---------------------------------------------------------------------------
__global__ __launch_bounds__(256) void rope_q(
    float* __restrict__ T, const float* __restrict__ cosT,
    const float* __restrict__ sinT)
{
    int idx = blockIdx.x * blockDim.x + threadIdx.x;
    int total = SEQ * NH * 64;
    if (idx >= total) return;
    int d = idx & 63;
    int h = (idx >> 6) % NH;
    int s = idx / (64 * NH);

    float* row = T + (size_t)s * DOUT + h * HD;
    float x1 = row[d];
    float x2 = row[d + 64];
    row[d]      = fmaf(x1, cosT[s * HD + d],      -x2 * sinT[s * HD + d]);
    row[d + 64] = fmaf(x2, cosT[s * HD + d + 64],  x1 * sinT[s * HD + d + 64]);
}

// RoPE for K: fp32 in, fp16 out
__global__ __launch_bounds__(256) void rope_k_h(
    const float* __restrict__ T, __half* __restrict__ Th,
    const float* __restrict__ cosT, const float* __restrict__ sinT)
{
    int idx = blockIdx.x * blockDim.x + threadIdx.x;
    int total = SEQ * NKV * 64;
    if (idx >= total) return;
    int d = idx & 63;
    int h = (idx >> 6) % NKV;
    int s = idx / (64 * NKV);

    const float* row = T + (size_t)s * (NKV * HD) + h * HD;
    __half* rowh = Th + (size_t)s * (NKV * HD) + h * HD;
    float x1 = row[d];
    float x2 = row[d + 64];
    rowh[d]      = __float2half_rn(fmaf(x1, cosT[s * HD + d],      -x2 * sinT[s * HD + d]));
    rowh[d + 64] = __float2half_rn(fmaf(x2, cosT[s * HD + d + 64],  x1 * sinT[s * HD + d + 64]));
}

// ---------------------------------------------------------------------------
// fp16 tensor-core flash attention (Round 12 — validated)
// ---------------------------------------------------------------------------
#define BQ   128
#define BKV  64
#define PSH  72
#define ATT_STAGE 32768
#define ATT_SMEM  (2 * ATT_STAGE + BQ * PSH * 2)

__global__ __launch_bounds__(256, 1) void attn_mma(
    const float* __restrict__ Q, const __half* __restrict__ Kh,
    const __half* __restrict__ Vt, __half* __restrict__ ctx)
{
    const int qb  = gridDim.x - 1 - blockIdx.x;
    const int h   = blockIdx.y;
    const int hk  = h >> 2;
    const int tid = threadIdx.x;
    const int lane = tid & 31;
    const int warp = tid >> 5;
    const int gID  = lane >> 2;
    const int tig  = lane & 3;
    const int wrow = warp * 16;

    extern __shared__ char smc[];
    const uint32_t sbase = smem_u32(smc);
    __half* Psh = (__half*)(smc + 2 * ATT_STAGE);

    const float scale = 0.08838834764831845f;

    auto fill = [&](int buf, int kb) {
        {
            const int r  = tid >> 2;
            const uint32_t kdst = sbase + buf * ATT_STAGE + r * 256;
            const __half* ksrc = Kh + (size_t)(kb * BKV + r) * (NKV * HD) + hk * HD;
#pragma unroll
            for (int j = 0; j < 4; j++) {
                const int ch = (tid & 3) * 4 + j;
                cp16(kdst + (uint32_t)((ch ^ (r & 7)) << 4), ksrc + ch * 8);
            }
        }
        {
            const int r  = tid >> 1;
            const uint32_t vdst = sbase + buf * ATT_STAGE + 16384 + r * 128;
            const __half* vsrc = Vt + (size_t)(hk * HD + r) * SEQ + kb * BKV;
#pragma unroll
            for (int j = 0; j < 4; j++) {
                const int ch = (tid & 1) * 4 + j;
                cp16(vdst + (uint32_t)((ch ^ (r & 7)) << 4), vsrc + ch * 8);
            }
        }
    };

    uint32_t qf[8][4];
    {
        const float* q0 = Q + (size_t)(qb * BQ + wrow + gID) * DOUT + h * HD;
        const float* q1 = q0 + (size_t)8 * DOUT;
#pragma unroll
        for (int kk = 0; kk < 8; kk++) {
            const int k = kk * 16;
            qf[kk][0] = pack_h2(q0[k + 2 * tig] * scale, q0[k + 2 * tig + 1] * scale);
            qf[kk][1] = pack_h2(q1[k + 2 * tig] * scale, q1[k + 2 * tig + 1] * scale);
            qf[kk][2] = pack_h2(q0[k + 8 + 2 * tig] * scale, q0[k + 9 + 2 * tig] * scale);
            qf[kk][3] = pack_h2(q1[k + 8 + 2 * tig] * scale, q1[k + 9 + 2 * tig] * scale);
        }
    }

    float mrow[2] = {-1e30f, -1e30f};
    float lrow[2] = {0.f, 0.f};
    float accO[16][4];
#pragma unroll
    for (int i = 0; i < 16; i++)
#pragma unroll
        for (int j = 0; j < 4; j++) accO[i][j] = 0.f;

    const int nkb = 2 * qb + 2;

    fill(0, 0);
    CP_COMMIT();

    for (int kb = 0; kb < nkb; kb++) {
        const int buf = kb & 1;
        if (kb + 1 < nkb) fill((kb + 1) & 1, kb + 1);
        CP_COMMIT();
        CP_WAIT(1);
        __syncthreads();

        const uint32_t* Ku = (const uint32_t*)(smc + buf * ATT_STAGE);
        const uint32_t* Vu = (const uint32_t*)(smc + buf * ATT_STAGE + 16384);

        float accS[8][4];
#pragma unroll
        for (int i = 0; i < 8; i++)
#pragma unroll
            for (int j = 0; j < 4; j++) accS[i][j] = 0.f;

#pragma unroll
        for (int kk = 0; kk < 8; kk++) {
            const int c0 = 2 * kk;
            const int c1 = 2 * kk + 1;
#pragma unroll
            for (int nt = 0; nt < 8; nt++) {
                const int n = nt * 8 + gID;
                uint32_t b[2];
                b[0] = Ku[n * 64 + ((c0 ^ gID) << 2) + tig];
                b[1] = Ku[n * 64 + ((c1 ^ gID) << 2) + tig];
                mma_f16(accS[nt], qf[kk], b);
            }
        }

        if (kb >= 2 * qb) {
            const int q0 = qb * BQ + wrow + gID;
            const int q1 = q0 + 8;
#pragma unroll
            for (int nt = 0; nt < 8; nt++) {
                const int kg = kb * BKV + nt * 8 + 2 * tig;
                if (kg > q0)     accS[nt][0] = -1e30f;
                if (kg + 1 > q0) accS[nt][1] = -1e30f;
                if (kg > q1)     accS[nt][2] = -1e30f;
                if (kg + 1 > q1) accS[nt][3] = -1e30f;
            }
        }

        float mx0 = -1e30f, mx1 = -1e30f;
#pragma unroll
        for (int nt = 0; nt < 8; nt++) {
            mx0 = fmaxf(mx0, fmaxf(accS[nt][0], accS[nt][1]));
            mx1 = fmaxf(mx1, fmaxf(accS[nt][2], accS[nt][3]));
        }
        mx0 = fmaxf(mx0, __shfl_xor_sync(0xffffffffu, mx0, 1));
        mx0 = fmaxf(mx0, __shfl_xor_sync(0xffffffffu, mx0, 2));
        mx1 = fmaxf(mx1, __shfl_xor_sync(0xffffffffu, mx1, 1));
        mx1 = fmaxf(mx1, __shfl_xor_sync(0xffffffffu, mx1, 2));

        float mn0 = fmaxf(mrow[0], mx0);
        float mn1 = fmaxf(mrow[1], mx1);
        float al0 = __expf(mrow[0] - mn0);
        float al1 = __expf(mrow[1] - mn1);
        mrow[0] = mn0; mrow[1] = mn1;

        float ls0 = 0.f, ls1 = 0.f;
        const int pr0 = wrow + gID;
#pragma unroll
        for (int nt = 0; nt < 8; nt++) {
            float p0 = __expf(accS[nt][0] - mn0);
            float p1 = __expf(accS[nt][1] - mn0);
            float p2 = __expf(accS[nt][2] - mn1);
            float p3 = __expf(accS[nt][3] - mn1);
            ls0 += p0 + p1;
            ls1 += p2 + p3;
            const int c = nt * 8 + 2 * tig;
            __half2 h0 = __floats2half2_rn(p0, p1);
            __half2 h1 = __floats2half2_rn(p2, p3);
            *(__half2*)(Psh + pr0 * PSH + c)       = h0;
            *(__half2*)(Psh + (pr0 + 8) * PSH + c) = h1;
        }
        ls0 += __shfl_xor_sync(0xffffffffu, ls0, 1);
        ls0 += __shfl_xor_sync(0xffffffffu, ls0, 2);
        ls1 += __shfl_xor_sync(0xffffffffu, ls1, 1);
        ls1 += __shfl_xor_sync(0xffffffffu, ls1, 2);
        lrow[0] = lrow[0] * al0 + ls0;
        lrow[1] = lrow[1] * al1 + ls1;

#pragma unroll
        for (int nt = 0; nt < 16; nt++) {
            accO[nt][0] *= al0; accO[nt][1] *= al0;
            accO[nt][2] *= al1; accO[nt][3] *= al1;
        }
        __syncwarp();

        const uint32_t* Pu = (const uint32_t*)Psh;
#pragma unroll
        for (int kk = 0; kk < 4; kk++) {
            const int c0 = 2 * kk;
            const int c1 = 2 * kk + 1;
            uint32_t a[4];
            a[0] = Pu[pr0 * (PSH / 2) + kk * 8 + tig];
            a[1] = Pu[(pr0 + 8) * (PSH / 2) + kk * 8 + tig];
            a[2] = Pu[pr0 * (PSH / 2) + kk * 8 + 4 + tig];
            a[3] = Pu[(pr0 + 8) * (PSH / 2) + kk * 8 + 4 + tig];
#pragma unroll
            for (int nt = 0; nt < 16; nt++) {
                const int n = nt * 8 + gID;
                uint32_t b[2];
                b[0] = Vu[n * 32 + ((c0 ^ gID) << 2) + tig];
                b[1] = Vu[n * 32 + ((c1 ^ gID) << 2) + tig];
                mma_f16(accO[nt], a, b);
            }
        }
        __syncthreads();
    }

    const float li0 = 1.f / lrow[0];
    const float li1 = 1.f / lrow[1];
    const int r0 = qb * BQ + wrow + gID;
    const int r1 = r0 + 8;
#pragma unroll
    for (int nt = 0; nt < 16; nt++) {
        const int c = h * HD + nt * 8 + 2 * tig;
        __half2 h0 = __floats2half2_rn(accO[nt][0] * li0, accO[nt][1] * li0);
        __half2 h1 = __floats2half2_rn(accO[nt][2] * li1, accO[nt][3] * li1);
        *(__half2*)(ctx + (size_t)r0 * DOUT + c) = h0;
        *(__half2*)(ctx + (size_t)r1 * DOUT + c) = h1;
    }
}

// ---------------------------------------------------------------------------
// Launch
// ---------------------------------------------------------------------------
extern "C" void kernel_launch(void* const* d_in, const int* in_sizes, int n_in,
                              void* d_out, int out_size)
{
    const float* x    = (const float*)d_in[0];
    const float* cosT = (const float*)d_in[1];
    const float* sinT = (const float*)d_in[2];
    const float* Wq   = (const float*)d_in[3];
    const float* Wk   = (const float*)d_in[4];
    const float* Wv   = (const float*)d_in[5];
    const float* Wo   = (const float*)d_in[6];
    float* out = (float*)d_out;

    float *Qp, *Kp, *Vp;
    __half *Kph, *Vtp, *Cph, *xh, *Wqh, *Wkh, *Wvh, *Woh;
    cudaGetSymbolAddress((void**)&Qp, g_Q);
    cudaGetSymbolAddress((void**)&Kp, g_K);
    cudaGetSymbolAddress((void**)&Vp, g_V);
    cudaGetSymbolAddress((void**)&Kph, g_Kh);
    cudaGetSymbolAddress((void**)&Vtp, g_Vth);
    cudaGetSymbolAddress((void**)&Cph, g_ctxh);
    cudaGetSymbolAddress((void**)&xh, g_xh);
    cudaGetSymbolAddress((void**)&Wqh, g_Wqh);
    cudaGetSymbolAddress((void**)&Wkh, g_Wkh);
    cudaGetSymbolAddress((void**)&Wvh, g_Wvh);
    cudaGetSymbolAddress((void**)&Woh, g_Woh);

    cudaFuncSetAttribute(gemm_qkv, cudaFuncAttributeMaxDynamicSharedMemorySize, GEMM_SMEM);
    cudaFuncSetAttribute(gemm_nt,  cudaFuncAttributeMaxDynamicSharedMemorySize, GEMM_SMEM);
    cudaFuncSetAttribute(attn_mma, cudaFuncAttributeMaxDynamicSharedMemorySize, ATT_SMEM);

    // Convert GEMM operands to fp16
    round_f16<<<2048, 256>>>(x,  xh,  (SEQ * DIN) / 4);
    round_f16<<<2048, 256>>>(Wq, Wqh, (DOUT * DIN) / 4);
    round_f16<<<2048, 256>>>(Wk, Wkh, ((NKV * HD) * DIN) / 4);
    round_f16<<<2048, 256>>>(Wv, Wvh, ((NKV * HD) * DIN) / 4);
    round_f16<<<2048, 256>>>(Wo, Woh, (DOUT * DOUT) / 4);

    // Fused QKV projection (fp16 in, fp32 out)
    gemm_qkv<<<dim3(48, SEQ / 128), 128, GEMM_SMEM>>>(xh, Wqh, Wkh, Wvh, Qp, Kp, Vp);

    // RoPE: Q fp32 in-place; K -> fp16 buffer
    {
        int totQ = SEQ * NH * 64;
        rope_q<<<(totQ + 255) / 256, 256>>>(Qp, cosT, sinT);
        int totK = SEQ * NKV * 64;
        rope_k_h<<<(totK + 255) / 256, 256>>>(Kp, Kph, cosT, sinT);
    }

    // V transpose -> fp16 [d][s]
    vtrans<<<dim3(SEQ / 32, (NKV * HD) / 32), 256>>>(Vp, Vtp);

    // fp16 tensor-core flash attention
    attn_mma<<<dim3(SEQ / BQ, NH), 256, ATT_SMEM>>>(Qp, Kph, Vtp, Cph);

    // Output projection (fp16 operands)
    gemm_nt<<<dim3(DOUT / 128, SEQ / 128), 128, GEMM_SMEM>>>(Cph, Woh, out, DIN, DOUT);
}

// round 14
// speedup vs baseline: 2.1917x; 1.0079x over previous
#include <cuda_runtime.h>
#include <cuda_fp16.h>
#include <math.h>
#include <stdint.h>

// Problem constants
#define SEQ    2048
#define DIN    4096
#define DOUT   4096
#define NH     32
#define NKV    8
#define HD     128
#define GROUP  4

// Scratch buffers
__device__ float  g_Q[SEQ * DOUT];
__device__ float  g_K[SEQ * (NKV * HD)];
__device__ float  g_V[SEQ * (NKV * HD)];
__device__ __half g_Kh[SEQ * (NKV * HD)];
__device__ __half g_Vth[(NKV * HD) * SEQ];
__device__ __half g_ctxh[SEQ * DOUT];
__device__ __half g_xh[SEQ * DIN];
__device__ __half g_Wqh[DOUT * DIN];
__device__ __half g_Wkh[(NKV * HD) * DIN];
__device__ __half g_Wvh[(NKV * HD) * DIN];
__device__ __half g_Woh[DOUT * DOUT];

// fp16 mma
__device__ __forceinline__ void mma_f16(float* c, const uint32_t* a, const uint32_t* b) {
    asm volatile(
        "mma.sync.aligned.m16n8k16.row.col.f32.f16.f16.f32 "
        "{%0,%1,%2,%3}, {%4,%5,%6,%7}, {%8,%9}, {%0,%1,%2,%3};"
        : "+f"(c[0]), "+f"(c[1]), "+f"(c[2]), "+f"(c[3])
        : "r"(a[0]), "r"(a[1]), "r"(a[2]), "r"(a[3]), "r"(b[0]), "r"(b[1]));
}

__device__ __forceinline__ void ldsm4(uint32_t* r, uint32_t addr) {
    asm volatile("ldmatrix.sync.aligned.m8n8.x4.shared.b16 {%0,%1,%2,%3}, [%4];"
        : "=r"(r[0]), "=r"(r[1]), "=r"(r[2]), "=r"(r[3]) : "r"(addr));
}

__device__ __forceinline__ uint32_t smem_u32(const void* p) {
    uint32_t a;
    asm("{ .reg .u64 t; cvta.to.shared.u64 t, %1; cvt.u32.u64 %0, t; }"
        : "=r"(a) : "l"(p));
    return a;
}

__device__ __forceinline__ void cp16(uint32_t dst, const void* src) {
    asm volatile("cp.async.cg.shared.global [%0], [%1], 16;"
                 :: "r"(dst), "l"(src) : "memory");
}
#define CP_COMMIT() asm volatile("cp.async.commit_group;" ::: "memory")
#define CP_WAIT(n)  asm volatile("cp.async.wait_group %0;" :: "n"(n) : "memory")

__device__ __forceinline__ uint32_t pack_h2(float a, float b) {
    __half2 h = __floats2half2_rn(a, b);
    return *(uint32_t*)&h;
}

// ---------------------------------------------------------------------------
// Batched fp32 -> fp16 conversion: all five tensors, one launch.
// Segments (in float4 units): x 2M | Wq 4M | Wk 1M | Wv 1M | Wo 4M
// ---------------------------------------------------------------------------
#define N4_X   ((SEQ * DIN) / 4)
#define N4_WQ  ((DOUT * DIN) / 4)
#define N4_WK  (((NKV * HD) * DIN) / 4)
#define N4_WV  (((NKV * HD) * DIN) / 4)
#define N4_WO  ((DOUT * DOUT) / 4)
#define N4_TOT (N4_X + N4_WQ + N4_WK + N4_WV + N4_WO)

__global__ __launch_bounds__(256) void round_f16_all(
    const float* __restrict__ x,  const float* __restrict__ Wq,
    const float* __restrict__ Wk, const float* __restrict__ Wv,
    const float* __restrict__ Wo,
    __half* __restrict__ xh,  __half* __restrict__ Wqh,
    __half* __restrict__ Wkh, __half* __restrict__ Wvh,
    __half* __restrict__ Woh)
{
    for (int i = blockIdx.x * blockDim.x + threadIdx.x; i < N4_TOT;
         i += gridDim.x * blockDim.x) {
        const float* in;
        __half* out;
        int j = i;
        if (j < N4_X)                 { in = x;  out = xh; }
        else if ((j -= N4_X)  < N4_WQ){ in = Wq; out = Wqh; }
        else if ((j -= N4_WQ) < N4_WK){ in = Wk; out = Wkh; }
        else if ((j -= N4_WK) < N4_WV){ in = Wv; out = Wvh; }
        else { j -= N4_WV;              in = Wo; out = Woh; }
        float4 v = *(const float4*)(in + (size_t)j * 4);
        __half2 h0 = __floats2half2_rn(v.x, v.y);
        __half2 h1 = __floats2half2_rn(v.z, v.w);
        *(uint2*)(out + (size_t)j * 4) =
            make_uint2(*(uint32_t*)&h0, *(uint32_t*)&h1);
    }
}

// ---------------------------------------------------------------------------
// V transpose: [SEQ][1024] fp32 -> [1024][SEQ] fp16
// ---------------------------------------------------------------------------
__global__ __launch_bounds__(256) void vtrans(
    const float* __restrict__ V, __half* __restrict__ Vt)
{
    __shared__ float t[32][33];
    const int s0 = blockIdx.x * 32;
    const int c0 = blockIdx.y * 32;
    const int tx = threadIdx.x & 31;
    const int ty = threadIdx.x >> 5;
#pragma unroll
    for (int i = ty; i < 32; i += 8)
        t[i][tx] = V[(size_t)(s0 + i) * (NKV * HD) + c0 + tx];
    __syncthreads();
#pragma unroll
    for (int i = ty; i < 32; i += 8)
        Vt[(size_t)(c0 + i) * SEQ + s0 + tx] = __float2half_rn(t[tx][i]);
}

// ===========================================================================
// fp16 GEMM core (Round 13 — validated)
// ===========================================================================
#define GS 3
#define STAGE_BYTES 32768
#define GEMM_SMEM (GS * STAGE_BYTES)

__device__ __forceinline__ void gemm_core_h(
    const __half* __restrict__ A, const __half* __restrict__ B,
    float* __restrict__ C, int K, int ldc, int bm)
{
    extern __shared__ char sbuf[];
    const uint32_t sbase = smem_u32(sbuf);
    const int tid  = threadIdx.x;
    const int lane = tid & 31;
    const int warp = tid >> 5;
    const int gID  = lane >> 2;
    const int tig  = lane & 3;
    const int wm   = (warp & 1) * 64;
    const int wn   = (warp >> 1) * 64;

    const int fr = tid >> 3;
    const int fc = tid & 7;

    const int l7    = lane & 7;
    const int aRowL = l7 + ((lane >> 3) & 1) * 8;
    const int aChO  = lane >> 4;
    const int bRowL = l7 + (lane >> 4) * 8;
    const int bChO  = (lane >> 3) & 1;

    float acc[4][8][4];
#pragma unroll
    for (int mi = 0; mi < 4; mi++)
#pragma unroll
        for (int ni = 0; ni < 8; ni++)
#pragma unroll
            for (int j = 0; j < 4; j++) acc[mi][ni][j] = 0.f;

    const int nK = K >> 6;

    auto fill = [&](int st, int kt) {
        const uint32_t dA = sbase + st * STAGE_BYTES;
        const uint32_t dB = dA + 16384;
        const __half* gA = A + (size_t)bm * K + kt * 64;
        const __half* gB = B + (size_t)kt * 64;
#pragma unroll
        for (int i = 0; i < 8; i++) {
            const int r = fr + i * 16;
            const uint32_t sw = (uint32_t)(r * 128 + ((fc ^ (r & 7)) * 16));
            cp16(dA + sw, gA + (size_t)r * K + fc * 8);
            cp16(dB + sw, gB + (size_t)r * K + fc * 8);
        }
    };

#pragma unroll
    for (int s = 0; s < GS - 1; s++) {
        if (s < nK) fill(s, s);
        CP_COMMIT();
    }

    for (int kt = 0; kt < nK; kt++) {
        const int nxt = kt + GS - 1;
        if (nxt < nK) fill(nxt % GS, nxt);
        CP_COMMIT();
        CP_WAIT(2);
        __syncthreads();

        const uint32_t sa = sbase + (kt % GS) * STAGE_BYTES;
        const uint32_t sb = sa + 16384;
        uint32_t aBase[4], bBase[4];
#pragma unroll
        for (int mi = 0; mi < 4; mi++)
            aBase[mi] = sa + (uint32_t)((wm + mi * 16 + aRowL) * 128);
#pragma unroll
        for (int nj = 0; nj < 4; nj++)
            bBase[nj] = sb + (uint32_t)((wn + nj * 16 + bRowL) * 128);

#pragma unroll
        for (int kk = 0; kk < 4; kk++) {
            const int chA = 2 * kk + aChO;
            const int chB = 2 * kk + bChO;
            const uint32_t swA = (uint32_t)((chA ^ l7) << 4);
            const uint32_t swB = (uint32_t)((chB ^ l7) << 4);

            uint32_t af[4][4], bf[8][2];
#pragma unroll
            for (int mi = 0; mi < 4; mi++)
                ldsm4(af[mi], aBase[mi] + swA);
#pragma unroll
            for (int nj = 0; nj < 4; nj++) {
                uint32_t tmp[4];
                ldsm4(tmp, bBase[nj] + swB);
                bf[2 * nj][0]     = tmp[0];
                bf[2 * nj][1]     = tmp[1];
                bf[2 * nj + 1][0] = tmp[2];
                bf[2 * nj + 1][1] = tmp[3];
            }
#pragma unroll
            for (int mi = 0; mi < 4; mi++)
#pragma unroll
                for (int ni = 0; ni < 8; ni++)
                    mma_f16(acc[mi][ni], af[mi], bf[ni]);
        }
        __syncthreads();
    }

#pragma unroll
    for (int mi = 0; mi < 4; mi++) {
        const int r0 = bm + wm + mi * 16 + gID;
#pragma unroll
        for (int ni = 0; ni < 8; ni++) {
            const int c0 = wn + ni * 8 + tig * 2;
            const float* c = acc[mi][ni];
            *(float2*)(C + (size_t)r0 * ldc + c0)       = make_float2(c[0], c[1]);
            *(float2*)(C + (size_t)(r0 + 8) * ldc + c0) = make_float2(c[2], c[3]);
        }
    }
}

__global__ __launch_bounds__(128, 2) void gemm_qkv(
    const __half* __restrict__ x,
    const __half* __restrict__ Wq, const __half* __restrict__ Wk,
    const __half* __restrict__ Wv,
    float* __restrict__ Q, float* __restrict__ Ko, float* __restrict__ Vo)
{
    const int bn = blockIdx.x;
    const int bm = blockIdx.y * 128;
    const __half* B;
    float* C;
    int ldc, coff;
    if (bn < 32)      { B = Wq; C = Q;  ldc = DOUT; coff = bn * 128; }
    else if (bn < 40) { B = Wk; C = Ko; ldc = NKV * HD; coff = (bn - 32) * 128; }
    else              { B = Wv; C = Vo; ldc = NKV * HD; coff = (bn - 40) * 128; }
    gemm_core_h(x, B + (size_t)coff * DIN, C + coff, DIN, ldc, bm);
}

__global__ __launch_bounds__(128, 2) void gemm_nt(
    const __half* __restrict__ A, const __half* __restrict__ B,
    float* __restrict__ C, int K, int N)
{
    const int coff = blockIdx.x * 128;
    gemm_core_h(A, B + (size_t)coff * K, C + coff, K, N, blockIdx.y * 128);
}

// RoPE for K: fp32 in, fp16 out
__global__ __launch_bounds__(256) void rope_k_h(
    const float* __restrict__ T, __half* __restrict__ Th,
    const float* __restrict__ cosT, const float* __restrict__ sinT)
{
    int idx = blockIdx.x * blockDim.x + threadIdx.x;
    int total = SEQ * NKV * 64;
    if (idx >= total) return;
    int d = idx & 63;
    int h = (idx >> 6) % NKV;
    int s = idx / (64 * NKV);

    const float* row = T + (size_t)s * (NKV * HD) + h * HD;
    __half* rowh = Th + (size_t)s * (NKV * HD) + h * HD;
    float x1 = row[d];
    float x2 = row[d + 64];
    rowh[d]      = __float2half_rn(fmaf(x1, cosT[s * HD + d],      -x2 * sinT[s * HD + d]));
    rowh[d + 64] = __float2half_rn(fmaf(x2, cosT[s * HD + d + 64],  x1 * sinT[s * HD + d + 64]));
}

// ---------------------------------------------------------------------------
// fp16 flash attention with FUSED Q-RoPE (Round 14).
// Q is the raw projection (no rope pass); the rope pair (d, d+64) maps to
// fragment k-steps (kk, kk+4) at the same lane offset, so rope happens in
// registers during the one-time Q-fragment build. Same fmaf sequence as the
// old rope_q kernel -> bit-identical numerics.
// ---------------------------------------------------------------------------
#define BQ   128
#define BKV  64
#define PSH  72
#define ATT_STAGE 32768
#define ATT_SMEM  (2 * ATT_STAGE + BQ * PSH * 2)

__global__ __launch_bounds__(256, 1) void attn_mma(
    const float* __restrict__ Q, const __half* __restrict__ Kh,
    const __half* __restrict__ Vt, __half* __restrict__ ctx,
    const float* __restrict__ cosT, const float* __restrict__ sinT)
{
    const int qb  = gridDim.x - 1 - blockIdx.x;
    const int h   = blockIdx.y;
    const int hk  = h >> 2;
    const int tid = threadIdx.x;
    const int lane = tid & 31;
    const int warp = tid >> 5;
    const int gID  = lane >> 2;
    const int tig  = lane & 3;
    const int wrow = warp * 16;

    extern __shared__ char smc[];
    const uint32_t sbase = smem_u32(smc);
    __half* Psh = (__half*)(smc + 2 * ATT_STAGE);

    const float scale = 0.08838834764831845f;

    auto fill = [&](int buf, int kb) {
        {
            const int r  = tid >> 2;
            const uint32_t kdst = sbase + buf * ATT_STAGE + r * 256;
            const __half* ksrc = Kh + (size_t)(kb * BKV + r) * (NKV * HD) + hk * HD;
#pragma unroll
            for (int j = 0; j < 4; j++) {
                const int ch = (tid & 3) * 4 + j;
                cp16(kdst + (uint32_t)((ch ^ (r & 7)) << 4), ksrc + ch * 8);
            }
        }
        {
            const int r  = tid >> 1;
            const uint32_t vdst = sbase + buf * ATT_STAGE + 16384 + r * 128;
            const __half* vsrc = Vt + (size_t)(hk * HD + r) * SEQ + kb * BKV;
#pragma unroll
            for (int j = 0; j < 4; j++) {
                const int ch = (tid & 1) * 4 + j;
                cp16(vdst + (uint32_t)((ch ^ (r & 7)) << 4), vsrc + ch * 8);
            }
        }
    };

    // ---- Q fragments: load raw, apply RoPE in registers, pack fp16 ----
    uint32_t qf[8][4];
    {
        const int s0 = qb * BQ + wrow + gID;
        const int s1 = s0 + 8;
        const float* q0 = Q + (size_t)s0 * DOUT + h * HD;
        const float* q1 = Q + (size_t)s1 * DOUT + h * HD;

        float r0[8][4], r1[8][4];
#pragma unroll
        for (int kk = 0; kk < 8; kk++) {
            const int k = kk * 16;
            r0[kk][0] = q0[k + 2 * tig];     r0[kk][1] = q0[k + 2 * tig + 1];
            r0[kk][2] = q0[k + 8 + 2 * tig]; r0[kk][3] = q0[k + 9 + 2 * tig];
            r1[kk][0] = q1[k + 2 * tig];     r1[kk][1] = q1[k + 2 * tig + 1];
            r1[kk][2] = q1[k + 8 + 2 * tig]; r1[kk][3] = q1[k + 9 + 2 * tig];
        }
        const int off[4] = {2 * tig, 2 * tig + 1, 8 + 2 * tig, 9 + 2 * tig};
#pragma unroll
        for (int kk = 0; kk < 4; kk++) {
#pragma unroll
            for (int j = 0; j < 4; j++) {
                const int d = kk * 16 + off[j];
                const float cL  = cosT[s0 * HD + d],      sL  = sinT[s0 * HD + d];
                const float cH  = cosT[s0 * HD + d + 64], sH  = sinT[s0 * HD + d + 64];
                const float cL1 = cosT[s1 * HD + d],      sL1 = sinT[s1 * HD + d];
                const float cH1 = cosT[s1 * HD + d + 64], sH1 = sinT[s1 * HD + d + 64];
                float lo, hi;
                lo = r0[kk][j]; hi = r0[kk + 4][j];
                r0[kk][j]     = fmaf(lo, cL, -hi * sL);
                r0[kk + 4][j] = fmaf(hi, cH,  lo * sH);
                lo = r1[kk][j]; hi = r1[kk + 4][j];
                r1[kk][j]     = fmaf(lo, cL1, -hi * sL1);
                r1[kk + 4][j] = fmaf(hi, cH1,  lo * sH1);
            }
        }
#pragma unroll
        for (int kk = 0; kk < 8; kk++) {
            qf[kk][0] = pack_h2(r0[kk][0] * scale, r0[kk][1] * scale);
            qf[kk][1] = pack_h2(r1[kk][0] * scale, r1[kk][1] * scale);
            qf[kk][2] = pack_h2(r0[kk][2] * scale, r0[kk][3] * scale);
            qf[kk][3] = pack_h2(r1[kk][2] * scale, r1[kk][3] * scale);
        }
    }

    float mrow[2] = {-1e30f, -1e30f};
    float lrow[2] = {0.f, 0.f};
    float accO[16][4];
#pragma unroll
    for (int i = 0; i < 16; i++)
#pragma unroll
        for (int j = 0; j < 4; j++) accO[i][j] = 0.f;

    const int nkb = 2 * qb + 2;

    fill(0, 0);
    CP_COMMIT();

    for (int kb = 0; kb < nkb; kb++) {
        const int buf = kb & 1;
        if (kb + 1 < nkb) fill((kb + 1) & 1, kb + 1);
        CP_COMMIT();
        CP_WAIT(1);
        __syncthreads();

        const uint32_t* Ku = (const uint32_t*)(smc + buf * ATT_STAGE);
        const uint32_t* Vu = (const uint32_t*)(smc + buf * ATT_STAGE + 16384);

        float accS[8][4];
#pragma unroll
        for (int i = 0; i < 8; i++)
#pragma unroll
            for (int j = 0; j < 4; j++) accS[i][j] = 0.f;

#pragma unroll
        for (int kk = 0; kk < 8; kk++) {
            const int c0 = 2 * kk;
            const int c1 = 2 * kk + 1;
#pragma unroll
            for (int nt = 0; nt < 8; nt++) {
                const int n = nt * 8 + gID;
                uint32_t b[2];
                b[0] = Ku[n * 64 + ((c0 ^ gID) << 2) + tig];
                b[1] = Ku[n * 64 + ((c1 ^ gID) << 2) + tig];
                mma_f16(accS[nt], qf[kk], b);
            }
        }

        if (kb >= 2 * qb) {
            const int q0 = qb * BQ + wrow + gID;
            const int q1 = q0 + 8;
#pragma unroll
            for (int nt = 0; nt < 8; nt++) {
                const int kg = kb * BKV + nt * 8 + 2 * tig;
                if (kg > q0)     accS[nt][0] = -1e30f;
                if (kg + 1 > q0) accS[nt][1] = -1e30f;
                if (kg > q1)     accS[nt][2] = -1e30f;
                if (kg + 1 > q1) accS[nt][3] = -1e30f;
            }
        }

        float mx0 = -1e30f, mx1 = -1e30f;
#pragma unroll
        for (int nt = 0; nt < 8; nt++) {
            mx0 = fmaxf(mx0, fmaxf(accS[nt][0], accS[nt][1]));
            mx1 = fmaxf(mx1, fmaxf(accS[nt][2], accS[nt][3]));
        }
        mx0 = fmaxf(mx0, __shfl_xor_sync(0xffffffffu, mx0, 1));
        mx0 = fmaxf(mx0, __shfl_xor_sync(0xffffffffu, mx0, 2));
        mx1 = fmaxf(mx1, __shfl_xor_sync(0xffffffffu, mx1, 1));
        mx1 = fmaxf(mx1, __shfl_xor_sync(0xffffffffu, mx1, 2));

        float mn0 = fmaxf(mrow[0], mx0);
        float mn1 = fmaxf(mrow[1], mx1);
        float al0 = __expf(mrow[0] - mn0);
        float al1 = __expf(mrow[1] - mn1);
        mrow[0] = mn0; mrow[1] = mn1;

        float ls0 = 0.f, ls1 = 0.f;
        const int pr0 = wrow + gID;
#pragma unroll
        for (int nt = 0; nt < 8; nt++) {
            float p0 = __expf(accS[nt][0] - mn0);
            float p1 = __expf(accS[nt][1] - mn0);
            float p2 = __expf(accS[nt][2] - mn1);
            float p3 = __expf(accS[nt][3] - mn1);
            ls0 += p0 + p1;
            ls1 += p2 + p3;
            const int c = nt * 8 + 2 * tig;
            __half2 h0 = __floats2half2_rn(p0, p1);
            __half2 h1 = __floats2half2_rn(p2, p3);
            *(__half2*)(Psh + pr0 * PSH + c)       = h0;
            *(__half2*)(Psh + (pr0 + 8) * PSH + c) = h1;
        }
        ls0 += __shfl_xor_sync(0xffffffffu, ls0, 1);
        ls0 += __shfl_xor_sync(0xffffffffu, ls0, 2);
        ls1 += __shfl_xor_sync(0xffffffffu, ls1, 1);
        ls1 += __shfl_xor_sync(0xffffffffu, ls1, 2);
        lrow[0] = lrow[0] * al0 + ls0;
        lrow[1] = lrow[1] * al1 + ls1;

#pragma unroll
        for (int nt = 0; nt < 16; nt++) {
            accO[nt][0] *= al0; accO[nt][1] *= al0;
            accO[nt][2] *= al1; accO[nt][3] *= al1;
        }
        __syncwarp();

        const uint32_t* Pu = (const uint32_t*)Psh;
#pragma unroll
        for (int kk = 0; kk < 4; kk++) {
            const int c0 = 2 * kk;
            const int c1 = 2 * kk + 1;
            uint32_t a[4];
            a[0] = Pu[pr0 * (PSH / 2) + kk * 8 + tig];
            a[1] = Pu[(pr0 + 8) * (PSH / 2) + kk * 8 + tig];
            a[2] = Pu[pr0 * (PSH / 2) + kk * 8 + 4 + tig];
            a[3] = Pu[(pr0 + 8) * (PSH / 2) + kk * 8 + 4 + tig];
#pragma unroll
            for (int nt = 0; nt < 16; nt++) {
                const int n = nt * 8 + gID;
                uint32_t b[2];
                b[0] = Vu[n * 32 + ((c0 ^ gID) << 2) + tig];
                b[1] = Vu[n * 32 + ((c1 ^ gID) << 2) + tig];
                mma_f16(accO[nt], a, b);
            }
        }
        __syncthreads();
    }

    const float li0 = 1.f / lrow[0];
    const float li1 = 1.f / lrow[1];
    const int r0 = qb * BQ + wrow + gID;
    const int r1 = r0 + 8;
#pragma unroll
    for (int nt = 0; nt < 16; nt++) {
        const int c = h * HD + nt * 8 + 2 * tig;
        __half2 h0 = __floats2half2_rn(accO[nt][0] * li0, accO[nt][1] * li0);
        __half2 h1 = __floats2half2_rn(accO[nt][2] * li1, accO[nt][3] * li1);
        *(__half2*)(ctx + (size_t)r0 * DOUT + c) = h0;
        *(__half2*)(ctx + (size_t)r1 * DOUT + c) = h1;
    }
}

// ---------------------------------------------------------------------------
// Launch
// ---------------------------------------------------------------------------
extern "C" void kernel_launch(void* const* d_in, const int* in_sizes, int n_in,
                              void* d_out, int out_size)
{
    const float* x    = (const float*)d_in[0];
    const float* cosT = (const float*)d_in[1];
    const float* sinT = (const float*)d_in[2];
    const float* Wq   = (const float*)d_in[3];
    const float* Wk   = (const float*)d_in[4];
    const float* Wv   = (const float*)d_in[5];
    const float* Wo   = (const float*)d_in[6];
    float* out = (float*)d_out;

    float *Qp, *Kp, *Vp;
    __half *Kph, *Vtp, *Cph, *xh, *Wqh, *Wkh, *Wvh, *Woh;
    cudaGetSymbolAddress((void**)&Qp, g_Q);
    cudaGetSymbolAddress((void**)&Kp, g_K);
    cudaGetSymbolAddress((void**)&Vp, g_V);
    cudaGetSymbolAddress((void**)&Kph, g_Kh);
    cudaGetSymbolAddress((void**)&Vtp, g_Vth);
    cudaGetSymbolAddress((void**)&Cph, g_ctxh);
    cudaGetSymbolAddress((void**)&xh, g_xh);
    cudaGetSymbolAddress((void**)&Wqh, g_Wqh);
    cudaGetSymbolAddress((void**)&Wkh, g_Wkh);
    cudaGetSymbolAddress((void**)&Wvh, g_Wvh);
    cudaGetSymbolAddress((void**)&Woh, g_Woh);

    cudaFuncSetAttribute(gemm_qkv, cudaFuncAttributeMaxDynamicSharedMemorySize, GEMM_SMEM);
    cudaFuncSetAttribute(gemm_nt,  cudaFuncAttributeMaxDynamicSharedMemorySize, GEMM_SMEM);
    cudaFuncSetAttribute(attn_mma, cudaFuncAttributeMaxDynamicSharedMemorySize, ATT_SMEM);

    // Batched fp32 -> fp16 conversion (one launch)
    round_f16_all<<<2048, 256>>>(x, Wq, Wk, Wv, Wo, xh, Wqh, Wkh, Wvh, Woh);

    // Fused QKV projection
    gemm_qkv<<<dim3(48, SEQ / 128), 128, GEMM_SMEM>>>(xh, Wqh, Wkh, Wvh, Qp, Kp, Vp);

    // K RoPE -> fp16; V transpose -> fp16 (Q rope fused into attention)
    {
        int totK = SEQ * NKV * 64;
        rope_k_h<<<(totK + 255) / 256, 256>>>(Kp, Kph, cosT, sinT);
    }
    vtrans<<<dim3(SEQ / 32, (NKV * HD) / 32), 256>>>(Vp, Vtp);

    // fp16 flash attention with fused Q-RoPE
    attn_mma<<<dim3(SEQ / BQ, NH), 256, ATT_SMEM>>>(Qp, Kph, Vtp, Cph, cosT, sinT);

    // Output projection
    gemm_nt<<<dim3(DOUT / 128, SEQ / 128), 128, GEMM_SMEM>>>(Cph, Woh, out, DIN, DOUT);
}